// round 1
// baseline (speedup 1.0000x reference)
#include <cuda_runtime.h>
#include <math.h>
#include <stdint.h>

// ---------------------------------------------------------------------------
// Problem constants
// ---------------------------------------------------------------------------
#define B_      8
#define C_      320
#define D_      32
#define H_      32
#define W_      16
#define L_      16384          // D*H*W
#define M_      131072         // B*L   (tokens)
#define HEADS_  10
#define HDIM_   32
#define NWIN_   4096           // B * 512 windows
#define QK_SCALE 0.17677669529663687f  // 1/sqrt(32)

// ---------------------------------------------------------------------------
// Scratch (static device globals; allocation APIs are forbidden)
// ---------------------------------------------------------------------------
__device__ float g_t   [(size_t)M_ * C_];     // residual stream (B,L,C)
__device__ float g_xw  [(size_t)M_ * C_];     // LN output (windowed or plain order)
__device__ float g_qkv [(size_t)M_ * 960];    // qkv, windowed rows
__device__ float g_attn[(size_t)M_ * C_];     // attention output, windowed rows
__device__ float g_mlp [(size_t)M_ * 1280];   // f1/gelu output

// ---------------------------------------------------------------------------
// Window geometry: windowed row index r -> source token row in (B,L,C)
// wi = wd*64 + wh*8 + ww ; n = td*8 + th*2 + tw ; l = d*512 + h*16 + w
// ---------------------------------------------------------------------------
__device__ __forceinline__ int win_src_row(int r, bool shift) {
    int b   = r >> 14;           // / 16384
    int rem = r & 16383;
    int wi  = rem >> 5;
    int n   = rem & 31;
    int d = ((wi >> 6) << 2)        + (n >> 3);
    int h = (((wi >> 3) & 7) << 2)  + ((n >> 1) & 3);
    int w = ((wi & 7) << 1)         + (n & 1);
    if (shift) { d = (d + 2) & 31; h = (h + 2) & 31; w = (w + 1) & 15; }
    return (b << 14) + (d << 9) + (h << 4) + w;
}

// ---------------------------------------------------------------------------
// Input transpose: x (B,C,L) -> g_t (B,L,C)
// ---------------------------------------------------------------------------
__global__ void k_tin(const float* __restrict__ x, float* __restrict__ t) {
    __shared__ float tile[32][33];
    int b  = blockIdx.z;
    int l0 = blockIdx.x * 32;
    int c0 = blockIdx.y * 32;
    int tx = threadIdx.x, ty = threadIdx.y;
    #pragma unroll
    for (int i = ty; i < 32; i += 8)
        tile[i][tx] = x[((size_t)(b * C_ + c0 + i)) * L_ + l0 + tx];
    __syncthreads();
    #pragma unroll
    for (int i = ty; i < 32; i += 8)
        t[((size_t)(b * L_ + l0 + i)) * C_ + c0 + tx] = tile[tx][i];
}

// Output transpose: g_t (B,L,C) -> out (B,C,L)
__global__ void k_tout(const float* __restrict__ t, float* __restrict__ o) {
    __shared__ float tile[32][33];
    int b  = blockIdx.z;
    int l0 = blockIdx.x * 32;
    int c0 = blockIdx.y * 32;
    int tx = threadIdx.x, ty = threadIdx.y;
    #pragma unroll
    for (int i = ty; i < 32; i += 8)
        tile[i][tx] = t[((size_t)(b * L_ + l0 + i)) * C_ + c0 + tx];
    __syncthreads();
    #pragma unroll
    for (int i = ty; i < 32; i += 8)
        o[((size_t)(b * C_ + c0 + i)) * L_ + l0 + tx] = tile[tx][i];
}

// ---------------------------------------------------------------------------
// LayerNorm (one warp per token).  WIN: gather through (shifted) window
// partition into windowed row order.  Else plain token order.
// ---------------------------------------------------------------------------
template<bool WIN, bool SHIFT>
__global__ void k_ln(const float* __restrict__ t, const float* __restrict__ gam,
                     const float* __restrict__ bet, float* __restrict__ out) {
    int warp = (blockIdx.x * blockDim.x + threadIdx.x) >> 5;
    int lane = threadIdx.x & 31;
    if (warp >= M_) return;
    int src = WIN ? win_src_row(warp, SHIFT) : warp;
    const float* row = t + (size_t)src * C_;
    float v[10];
    float s = 0.f;
    #pragma unroll
    for (int i = 0; i < 10; i++) { v[i] = row[lane + 32 * i]; s += v[i]; }
    #pragma unroll
    for (int o = 16; o; o >>= 1) s += __shfl_xor_sync(0xffffffffu, s, o);
    float mu = s * (1.f / C_);
    float var = 0.f;
    #pragma unroll
    for (int i = 0; i < 10; i++) { float d = v[i] - mu; var += d * d; }
    #pragma unroll
    for (int o = 16; o; o >>= 1) var += __shfl_xor_sync(0xffffffffu, var, o);
    float inv = rsqrtf(var * (1.f / C_) + 1e-5f);
    float* orow = out + (size_t)warp * C_;
    #pragma unroll
    for (int i = 0; i < 10; i++) {
        int c = lane + 32 * i;
        orow[c] = (v[i] - mu) * inv * gam[c] + bet[c];
    }
}

// ---------------------------------------------------------------------------
// SGEMM  C[M_,Nn] = A[M_,K] @ Bm[K,Nn] (+bias, epilogue variants)
// BM=128, BN=64, BK=16, 256 threads, 8x4 micro-tile.
// EPI: 0 = store (+bias)          : Out[gm*Nn+gn] = v
//      1 = store gelu(v+bias)
//      2 = residual window-reverse scatter (+=) into Out (g_t), Nn==320
//      3 = residual plain (+=) into Out (g_t), Nn==320
// ---------------------------------------------------------------------------
template<int EPI, bool SHIFT>
__global__ __launch_bounds__(256)
void k_gemm(const float* __restrict__ A, const float* __restrict__ Bm,
            const float* __restrict__ bias, float* __restrict__ Out,
            int K, int Nn) {
    __shared__ float As[16][128];
    __shared__ float Bs[16][64];
    int tid = threadIdx.x;
    int m0 = blockIdx.y * 128;
    int n0 = blockIdx.x * 64;
    int ty = tid >> 4;     // 0..15 -> 8 rows each
    int tx = tid & 15;     // 0..15 -> 4 cols each

    float acc[8][4];
    #pragma unroll
    for (int i = 0; i < 8; i++)
        #pragma unroll
        for (int j = 0; j < 4; j++) acc[i][j] = 0.f;

    for (int k0 = 0; k0 < K; k0 += 16) {
        // load A tile 128x16 (2 float4 per thread), store transposed
        #pragma unroll
        for (int r = 0; r < 2; r++) {
            int vidx = tid + r * 256;
            int row = vidx >> 2;
            int c4  = (vidx & 3) * 4;
            float4 a = *(const float4*)(A + (size_t)(m0 + row) * K + k0 + c4);
            As[c4 + 0][row] = a.x; As[c4 + 1][row] = a.y;
            As[c4 + 2][row] = a.z; As[c4 + 3][row] = a.w;
        }
        // load B tile 16x64 (1 float4 per thread)
        {
            int brow = tid >> 4;
            int bc   = (tid & 15) * 4;
            float4 b = *(const float4*)(Bm + (size_t)(k0 + brow) * Nn + n0 + bc);
            *(float4*)&Bs[brow][bc] = b;
        }
        __syncthreads();
        #pragma unroll
        for (int kk = 0; kk < 16; kk++) {
            float4 a0 = *(const float4*)&As[kk][ty * 8];
            float4 a1 = *(const float4*)&As[kk][ty * 8 + 4];
            float4 b  = *(const float4*)&Bs[kk][tx * 4];
            float ar[8] = {a0.x, a0.y, a0.z, a0.w, a1.x, a1.y, a1.z, a1.w};
            float br[4] = {b.x, b.y, b.z, b.w};
            #pragma unroll
            for (int i = 0; i < 8; i++)
                #pragma unroll
                for (int j = 0; j < 4; j++)
                    acc[i][j] += ar[i] * br[j];
        }
        __syncthreads();
    }

    #pragma unroll
    for (int i = 0; i < 8; i++) {
        int gm = m0 + ty * 8 + i;
        size_t dstrow;
        if (EPI == 2) dstrow = (size_t)win_src_row(gm, SHIFT);
        else          dstrow = (size_t)gm;
        #pragma unroll
        for (int j = 0; j < 4; j++) {
            int gn = n0 + tx * 4 + j;
            float v = acc[i][j] + bias[gn];
            if (EPI == 1) v = 0.5f * v * (1.f + erff(v * 0.70710678118654752f));
            if (EPI == 2 || EPI == 3) {
                float* p = Out + dstrow * (size_t)Nn + gn;
                *p = *p + v;
            } else {
                Out[(size_t)gm * Nn + gn] = v;
            }
        }
    }
}

// ---------------------------------------------------------------------------
// Windowed attention: one warp per (window, head).  2 warps per block.
// qkv rows: [q(320) | k(320) | v(320)], columns head-major, dim minor.
// ---------------------------------------------------------------------------
template<bool SHIFT>
__global__ void k_attn(const float* __restrict__ qkv,
                       const float* __restrict__ biasTab,
                       float* __restrict__ out) {
    __shared__ float bias_sh[147 * 10];
    __shared__ float bufA[2][32 * 33];   // q, later o
    __shared__ float bufB[2][32 * 33];   // k, later v
    int tid  = threadIdx.x;
    int lane = tid & 31;
    int wrp  = tid >> 5;
    for (int i = tid; i < 1470; i += 64) bias_sh[i] = biasTab[i];
    __syncthreads();

    int g    = blockIdx.x * 2 + wrp;     // window-head id
    int win  = g / 10;
    int head = g - win * 10;
    const float* base = qkv + (size_t)win * 32 * 960;
    float* qs = bufA[wrp];
    float* ks = bufB[wrp];

    // coalesced staging of k and q
    #pragma unroll 4
    for (int m = 0; m < 32; m++) ks[m * 33 + lane] = base[m * 960 + 320 + head * 32 + lane];
    #pragma unroll 4
    for (int m = 0; m < 32; m++) qs[m * 33 + lane] = base[m * 960 +       head * 32 + lane];
    __syncwarp();

    float q[32];
    #pragma unroll
    for (int d = 0; d < 32; d++) q[d] = qs[lane * 33 + d] * QK_SCALE;

    // shift-mask region id for this lane's token (original coordinates)
    int myreg = 0;
    if (SHIFT) {
        int wi = win & 511;
        int d = ((wi >> 6) << 2)       + (lane >> 3);
        int h = (((wi >> 3) & 7) << 2) + ((lane >> 1) & 3);
        int w = ((wi & 7) << 1)        + (lane & 1);
        int rd = d < 28 ? 0 : (d < 30 ? 1 : 2);
        int rh = h < 28 ? 0 : (h < 30 ? 1 : 2);
        int rw = w < 14 ? 0 : (w < 15 ? 1 : 2);
        myreg = rd * 9 + rh * 3 + rw;
    }

    int tdn = lane >> 3, thn = (lane >> 1) & 3, twn = lane & 1;
    float s[32];
    #pragma unroll
    for (int m = 0; m < 32; m++) {
        float a = 0.f;
        #pragma unroll
        for (int d = 0; d < 32; d++) a += q[d] * ks[m * 33 + d];
        int idx = (tdn - (m >> 3) + 3) * 21 + (thn - ((m >> 1) & 3) + 3) * 3
                + (twn - (m & 1) + 1);
        a += bias_sh[idx * 10 + head];
        if (SHIFT) {
            int rm = __shfl_sync(0xffffffffu, myreg, m);
            if (rm != myreg) a -= 100.f;
        }
        s[m] = a;
    }

    float mx = -1e30f;
    #pragma unroll
    for (int m = 0; m < 32; m++) mx = fmaxf(mx, s[m]);
    float sum = 0.f;
    #pragma unroll
    for (int m = 0; m < 32; m++) { s[m] = __expf(s[m] - mx); sum += s[m]; }
    float inv = 1.f / sum;

    // load v into the k buffer (k no longer needed)
    __syncwarp();
    #pragma unroll 4
    for (int m = 0; m < 32; m++) ks[m * 33 + lane] = base[m * 960 + 640 + head * 32 + lane];
    __syncwarp();

    float o[32];
    #pragma unroll
    for (int d = 0; d < 32; d++) o[d] = 0.f;
    #pragma unroll
    for (int m = 0; m < 32; m++) {
        float p = s[m] * inv;
        #pragma unroll
        for (int d = 0; d < 32; d++) o[d] += p * ks[m * 33 + d];
    }

    // transpose through smem for coalesced store
    __syncwarp();
    #pragma unroll
    for (int d = 0; d < 32; d++) qs[lane * 33 + d] = o[d];
    __syncwarp();
    float* obase = out + (size_t)win * 32 * 320 + head * 32;
    #pragma unroll 4
    for (int m = 0; m < 32; m++) obase[m * 320 + lane] = qs[m * 33 + lane];
}

// ---------------------------------------------------------------------------
// Host-side orchestration
// ---------------------------------------------------------------------------
static void run_block(bool shift, const float* const* p,
                      float* t, float* xw, float* qkv, float* attn, float* mlp) {
    const float* ln1g = p[0];  const float* ln1b = p[1];
    const float* qkvw = p[2];  const float* qkvb = p[3];
    const float* bias = p[4];
    const float* projw = p[5]; const float* projb = p[6];
    const float* ln2g = p[7];  const float* ln2b = p[8];
    const float* f1w = p[9];   const float* f1b = p[10];
    const float* f2w = p[11];  const float* f2b = p[12];

    // LN1 + shift + window partition
    if (shift) k_ln<true, true ><<<16384, 256>>>(t, ln1g, ln1b, xw);
    else       k_ln<true, false><<<16384, 256>>>(t, ln1g, ln1b, xw);

    // QKV GEMM: (M,320) @ (320,960)
    k_gemm<0, false><<<dim3(960 / 64, M_ / 128), 256>>>(xw, qkvw, qkvb, qkv, 320, 960);

    // Attention: 40960 window-heads, 2 per block
    if (shift) k_attn<true ><<<20480, 64>>>(qkv, bias, attn);
    else       k_attn<false><<<20480, 64>>>(qkv, bias, attn);

    // proj GEMM + window-reverse + residual into t
    if (shift) k_gemm<2, true ><<<dim3(320 / 64, M_ / 128), 256>>>(attn, projw, projb, t, 320, 320);
    else       k_gemm<2, false><<<dim3(320 / 64, M_ / 128), 256>>>(attn, projw, projb, t, 320, 320);

    // LN2 (plain order)
    k_ln<false, false><<<16384, 256>>>(t, ln2g, ln2b, xw);

    // f1 GEMM + exact GELU
    k_gemm<1, false><<<dim3(1280 / 64, M_ / 128), 256>>>(xw, f1w, f1b, mlp, 320, 1280);

    // f2 GEMM + residual into t
    k_gemm<3, false><<<dim3(320 / 64, M_ / 128), 256>>>(mlp, f2w, f2b, t, 1280, 320);
}

extern "C" void kernel_launch(void* const* d_in, const int* in_sizes, int n_in,
                              void* d_out, int out_size) {
    (void)in_sizes; (void)n_in; (void)out_size;
    const float* x = (const float*)d_in[0];

    void *pt, *pxw, *pqkv, *pattn, *pmlp;
    cudaGetSymbolAddress(&pt,    g_t);
    cudaGetSymbolAddress(&pxw,   g_xw);
    cudaGetSymbolAddress(&pqkv,  g_qkv);
    cudaGetSymbolAddress(&pattn, g_attn);
    cudaGetSymbolAddress(&pmlp,  g_mlp);
    float* t    = (float*)pt;
    float* xw   = (float*)pxw;
    float* qkv  = (float*)pqkv;
    float* attn = (float*)pattn;
    float* mlp  = (float*)pmlp;

    // (B,C,L) -> (B,L,C)
    k_tin<<<dim3(L_ / 32, C_ / 32, B_), dim3(32, 8)>>>(x, t);

    const float* b1[13], * b2[13];
    for (int i = 0; i < 13; i++) b1[i] = (const float*)d_in[1 + i];
    for (int i = 0; i < 13; i++) b2[i] = (const float*)d_in[14 + i];

    run_block(false, b1, t, xw, qkv, attn, mlp);
    run_block(true,  b2, t, xw, qkv, attn, mlp);

    // (B,L,C) -> (B,C,L) into d_out
    k_tout<<<dim3(L_ / 32, C_ / 32, B_), dim3(32, 8)>>>(t, (float*)d_out);
}

// round 4
// speedup vs baseline: 3.2789x; 3.2789x over previous
#include <cuda_runtime.h>
#include <cuda_bf16.h>
#include <math.h>
#include <stdint.h>

// ---------------------------------------------------------------------------
// Problem constants
// ---------------------------------------------------------------------------
#define B_      8
#define C_      320
#define D_      32
#define H_      32
#define W_      16
#define L_      16384          // D*H*W
#define M_      131072         // B*L   (tokens)
#define QK_SCALE 0.17677669529663687f  // 1/sqrt(32)

typedef __nv_bfloat16 bf16;

// ---------------------------------------------------------------------------
// Portable tensor-core PTX helpers (sm_80+ ISA; works at target sm_100)
// ---------------------------------------------------------------------------
__device__ __forceinline__ uint32_t smem_to_u32(const void* p) {
    uint32_t a;
    asm("{ .reg .u64 t; cvta.to.shared.u64 t, %1; cvt.u32.u64 %0, t; }" : "=r"(a) : "l"(p));
    return a;
}
__device__ __forceinline__ void cp_async16(uint32_t dst, const void* src) {
    asm volatile("cp.async.cg.shared.global [%0], [%1], 16;" :: "r"(dst), "l"(src));
}
#define CP_COMMIT() asm volatile("cp.async.commit_group;" ::: "memory")
#define CP_WAIT1()  asm volatile("cp.async.wait_group 1;" ::: "memory")
#define CP_WAIT0()  asm volatile("cp.async.wait_group 0;" ::: "memory")

#define LDSM_X4(r0, r1, r2, r3, a) \
    asm volatile("ldmatrix.sync.aligned.m8n8.x4.shared.b16 {%0,%1,%2,%3}, [%4];" \
                 : "=r"(r0), "=r"(r1), "=r"(r2), "=r"(r3) : "r"(a))
#define LDSM_X2(r0, r1, a) \
    asm volatile("ldmatrix.sync.aligned.m8n8.x2.shared.b16 {%0,%1}, [%2];" \
                 : "=r"(r0), "=r"(r1) : "r"(a))

__device__ __forceinline__ void mma_16816(float* c, const uint32_t* a, const uint32_t* b) {
    asm volatile(
        "mma.sync.aligned.m16n8k16.row.col.f32.bf16.bf16.f32 "
        "{%0,%1,%2,%3}, {%4,%5,%6,%7}, {%8,%9}, {%0,%1,%2,%3};"
        : "+f"(c[0]), "+f"(c[1]), "+f"(c[2]), "+f"(c[3])
        : "r"(a[0]), "r"(a[1]), "r"(a[2]), "r"(a[3]), "r"(b[0]), "r"(b[1]));
}

// ---------------------------------------------------------------------------
// Scratch (static device globals)
// ---------------------------------------------------------------------------
__device__ float g_t   [(size_t)M_ * C_];      // residual stream fp32 (B,L,C)
__device__ bf16  g_xw  [(size_t)M_ * C_];      // LN output bf16
__device__ bf16  g_qkv [(size_t)M_ * 960];     // qkv bf16, windowed rows
__device__ bf16  g_attn[(size_t)M_ * C_];      // attention out bf16, windowed rows
__device__ bf16  g_mlp [(size_t)M_ * 1280];    // gelu(f1) out bf16
__device__ bf16  g_wb[2][1228800];             // [N,K] bf16 weights per block
#define WOFF_QKV 0
#define WOFF_PROJ 307200
#define WOFF_F1 409600
#define WOFF_F2 819200

// ---------------------------------------------------------------------------
// Window geometry
// ---------------------------------------------------------------------------
__device__ __forceinline__ int win_src_row(int r, bool shift) {
    int b   = r >> 14;
    int rem = r & 16383;
    int wi  = rem >> 5;
    int n   = rem & 31;
    int d = ((wi >> 6) << 2)        + (n >> 3);
    int h = (((wi >> 3) & 7) << 2)  + ((n >> 1) & 3);
    int w = ((wi & 7) << 1)         + (n & 1);
    if (shift) { d = (d + 2) & 31; h = (h + 2) & 31; w = (w + 1) & 15; }
    return (b << 14) + (d << 9) + (h << 4) + w;
}

// ---------------------------------------------------------------------------
// Transposes (fp32)
// ---------------------------------------------------------------------------
__global__ void k_tin(const float* __restrict__ x, float* __restrict__ t) {
    __shared__ float tile[32][33];
    int b = blockIdx.z, l0 = blockIdx.x * 32, c0 = blockIdx.y * 32;
    int tx = threadIdx.x, ty = threadIdx.y;
    #pragma unroll
    for (int i = ty; i < 32; i += 8)
        tile[i][tx] = x[((size_t)(b * C_ + c0 + i)) * L_ + l0 + tx];
    __syncthreads();
    #pragma unroll
    for (int i = ty; i < 32; i += 8)
        t[((size_t)(b * L_ + l0 + i)) * C_ + c0 + tx] = tile[tx][i];
}
__global__ void k_tout(const float* __restrict__ t, float* __restrict__ o) {
    __shared__ float tile[32][33];
    int b = blockIdx.z, l0 = blockIdx.x * 32, c0 = blockIdx.y * 32;
    int tx = threadIdx.x, ty = threadIdx.y;
    #pragma unroll
    for (int i = ty; i < 32; i += 8)
        tile[i][tx] = t[((size_t)(b * L_ + l0 + i)) * C_ + c0 + tx];
    __syncthreads();
    #pragma unroll
    for (int i = ty; i < 32; i += 8)
        o[((size_t)(b * C_ + c0 + i)) * L_ + l0 + tx] = tile[tx][i];
}

// ---------------------------------------------------------------------------
// Weight convert + transpose: W[K,N] fp32 -> out[N,K] bf16
// ---------------------------------------------------------------------------
__global__ void k_wconv(const float* __restrict__ Wm, bf16* __restrict__ out, int K, int N) {
    __shared__ float tile[32][33];
    int k0 = blockIdx.x * 32, n0 = blockIdx.y * 32;
    int tx = threadIdx.x, ty = threadIdx.y;
    #pragma unroll
    for (int i = ty; i < 32; i += 8)
        tile[i][tx] = Wm[(size_t)(k0 + i) * N + n0 + tx];
    __syncthreads();
    #pragma unroll
    for (int i = ty; i < 32; i += 8)
        out[(size_t)(n0 + i) * K + k0 + tx] = __float2bfloat16(tile[tx][i]);
}

// ---------------------------------------------------------------------------
// LayerNorm (one warp per token) -> bf16, optional windowed gather
// ---------------------------------------------------------------------------
template<bool WIN, bool SHIFT>
__global__ void k_ln(const float* __restrict__ t, const float* __restrict__ gam,
                     const float* __restrict__ bet, bf16* __restrict__ out) {
    int warp = (blockIdx.x * blockDim.x + threadIdx.x) >> 5;
    int lane = threadIdx.x & 31;
    if (warp >= M_) return;
    int src = WIN ? win_src_row(warp, SHIFT) : warp;
    const float* row = t + (size_t)src * C_;
    float v[10]; float s = 0.f;
    #pragma unroll
    for (int i = 0; i < 10; i++) { v[i] = row[lane + 32 * i]; s += v[i]; }
    #pragma unroll
    for (int o = 16; o; o >>= 1) s += __shfl_xor_sync(0xffffffffu, s, o);
    float mu = s * (1.f / C_); float var = 0.f;
    #pragma unroll
    for (int i = 0; i < 10; i++) { float d = v[i] - mu; var += d * d; }
    #pragma unroll
    for (int o = 16; o; o >>= 1) var += __shfl_xor_sync(0xffffffffu, var, o);
    float inv = rsqrtf(var * (1.f / C_) + 1e-5f);
    bf16* orow = out + (size_t)warp * C_;
    #pragma unroll
    for (int i = 0; i < 10; i++) {
        int c = lane + 32 * i;
        orow[c] = __float2bfloat16((v[i] - mu) * inv * gam[c] + bet[c]);
    }
}

// ---------------------------------------------------------------------------
// HMMA GEMM: Out[M_,Nn] = A[M_,K](bf16) @ Wt[Nn,K]^T(bf16) (+bias, epilogue)
// BM=128, BN=64, BK=32.  256 threads (8 warps, 4x2), warp tile 32x32.
// cp.async double-buffered smem; 40-bf16 padded rows (conflict-free ldmatrix).
// EPI: 0 = bf16 store (+bias)
//      1 = bf16 store gelu(v+bias)
//      2 = fp32 += into Out at window-reversed row (Nn==320)
//      3 = fp32 += into Out plain row (Nn==320)
// ---------------------------------------------------------------------------
#define LDA 40   // padded row stride (bf16 elems) for smem tiles

template<int EPI, bool SHIFT>
__global__ __launch_bounds__(256, 2)
void k_gemm_mma(const bf16* __restrict__ A, const bf16* __restrict__ Wt,
                const float* __restrict__ bias, void* __restrict__ OutP,
                int K, int Nn) {
    __shared__ __align__(16) bf16 As[2][128 * LDA];
    __shared__ __align__(16) bf16 Bs[2][64 * LDA];

    const int tid = threadIdx.x, lane = tid & 31, wid = tid >> 5;
    const int wm = wid & 3, wn = wid >> 2;           // 4 x 2 warp grid
    const int m0 = blockIdx.y * 128, n0 = blockIdx.x * 64;

    const uint32_t sA[2] = { smem_to_u32(As[0]), smem_to_u32(As[1]) };
    const uint32_t sB[2] = { smem_to_u32(Bs[0]), smem_to_u32(Bs[1]) };

    float acc[2][4][4];
    #pragma unroll
    for (int i = 0; i < 2; i++)
        #pragma unroll
        for (int j = 0; j < 4; j++)
            #pragma unroll
            for (int k = 0; k < 4; k++) acc[i][j][k] = 0.f;

    const int NC = K >> 5;   // chunks of 32

    // issue loads for chunk kc into buffer buf
    auto issue = [&](int kc, int buf) {
        const bf16* Ag = A + (size_t)m0 * K + kc * 32;
        #pragma unroll
        for (int i = 0; i < 2; i++) {
            int v = tid + i * 256;
            int row = v >> 2, c8 = (v & 3) * 8;
            cp_async16(sA[buf] + (uint32_t)(row * LDA + c8) * 2,
                       Ag + (size_t)row * K + c8);
        }
        const bf16* Bg = Wt + (size_t)n0 * K + kc * 32;
        {
            int row = tid >> 2, c8 = (tid & 3) * 8;
            cp_async16(sB[buf] + (uint32_t)(row * LDA + c8) * 2,
                       Bg + (size_t)row * K + c8);
        }
    };

    issue(0, 0);
    CP_COMMIT();

    for (int kc = 0; kc < NC; kc++) {
        int buf = kc & 1;
        if (kc + 1 < NC) { issue(kc + 1, buf ^ 1); CP_COMMIT(); CP_WAIT1(); }
        else             { CP_WAIT0(); }
        __syncthreads();

        #pragma unroll
        for (int ks = 0; ks < 2; ks++) {
            int k0 = ks * 16;
            uint32_t afr[2][4];
            #pragma unroll
            for (int mt = 0; mt < 2; mt++) {
                uint32_t addr = sA[buf] +
                    (uint32_t)(((wm * 32 + mt * 16 + (lane & 15)) * LDA)
                               + k0 + ((lane >> 4) * 8)) * 2;
                LDSM_X4(afr[mt][0], afr[mt][1], afr[mt][2], afr[mt][3], addr);
            }
            uint32_t bfr[4][2];
            #pragma unroll
            for (int nt = 0; nt < 4; nt++) {
                uint32_t addr = sB[buf] +
                    (uint32_t)(((wn * 32 + nt * 8 + (lane & 7)) * LDA)
                               + k0 + (((lane & 15) >> 3) * 8)) * 2;
                LDSM_X2(bfr[nt][0], bfr[nt][1], addr);
            }
            #pragma unroll
            for (int mt = 0; mt < 2; mt++)
                #pragma unroll
                for (int nt = 0; nt < 4; nt++)
                    mma_16816(acc[mt][nt], afr[mt], bfr[nt]);
        }
        __syncthreads();
    }

    // Epilogue: c-frag: regs {0,1}->row t/4, {2,3}->row t/4+8; cols (t%4)*2 +{0,1}
    const int qr = lane >> 2, qc = (lane & 3) * 2;
    #pragma unroll
    for (int nt = 0; nt < 4; nt++) {
        int gn = n0 + wn * 32 + nt * 8 + qc;
        float b0 = bias[gn], b1 = bias[gn + 1];
        #pragma unroll
        for (int mt = 0; mt < 2; mt++) {
            int gmA = m0 + wm * 32 + mt * 16 + qr;
            float v0 = acc[mt][nt][0] + b0;
            float v1 = acc[mt][nt][1] + b1;
            float v2 = acc[mt][nt][2] + b0;
            float v3 = acc[mt][nt][3] + b1;
            if (EPI == 1) {
                v0 = 0.5f * v0 * (1.f + erff(v0 * 0.70710678118654752f));
                v1 = 0.5f * v1 * (1.f + erff(v1 * 0.70710678118654752f));
                v2 = 0.5f * v2 * (1.f + erff(v2 * 0.70710678118654752f));
                v3 = 0.5f * v3 * (1.f + erff(v3 * 0.70710678118654752f));
            }
            if (EPI == 0 || EPI == 1) {
                bf16* Ob = (bf16*)OutP;
                __nv_bfloat162* p0 = (__nv_bfloat162*)(Ob + (size_t)gmA * Nn + gn);
                *p0 = __floats2bfloat162_rn(v0, v1);
                __nv_bfloat162* p1 = (__nv_bfloat162*)(Ob + (size_t)(gmA + 8) * Nn + gn);
                *p1 = __floats2bfloat162_rn(v2, v3);
            } else {
                float* Of = (float*)OutP;
                int r0 = (EPI == 2) ? win_src_row(gmA, SHIFT) : gmA;
                int r1 = (EPI == 2) ? win_src_row(gmA + 8, SHIFT) : (gmA + 8);
                float* p0 = Of + (size_t)r0 * 320 + gn;
                float* p1 = Of + (size_t)r1 * 320 + gn;
                p0[0] += v0; p0[1] += v1;
                p1[0] += v2; p1[1] += v3;
            }
        }
    }
}

// ---------------------------------------------------------------------------
// Windowed attention: one warp per (window, head), bf16 I/O
// ---------------------------------------------------------------------------
template<bool SHIFT>
__global__ void k_attn(const bf16* __restrict__ qkv,
                       const float* __restrict__ biasTab,
                       bf16* __restrict__ out) {
    __shared__ float bias_sh[147 * 10];
    __shared__ float bufA[2][32 * 33];
    __shared__ float bufB[2][32 * 33];
    int tid = threadIdx.x, lane = tid & 31, wrp = tid >> 5;
    for (int i = tid; i < 1470; i += 64) bias_sh[i] = biasTab[i];
    __syncthreads();

    int g = blockIdx.x * 2 + wrp;
    int win = g / 10;
    int head = g - win * 10;
    const bf16* base = qkv + (size_t)win * 32 * 960;
    float* qs = bufA[wrp];
    float* ks = bufB[wrp];

    #pragma unroll 4
    for (int m = 0; m < 32; m++) ks[m * 33 + lane] = __bfloat162float(base[m * 960 + 320 + head * 32 + lane]);
    #pragma unroll 4
    for (int m = 0; m < 32; m++) qs[m * 33 + lane] = __bfloat162float(base[m * 960 +       head * 32 + lane]);
    __syncwarp();

    float q[32];
    #pragma unroll
    for (int d = 0; d < 32; d++) q[d] = qs[lane * 33 + d] * QK_SCALE;

    int myreg = 0;
    if (SHIFT) {
        int wi = win & 511;
        int d = ((wi >> 6) << 2)       + (lane >> 3);
        int h = (((wi >> 3) & 7) << 2) + ((lane >> 1) & 3);
        int w = ((wi & 7) << 1)        + (lane & 1);
        int rd = d < 28 ? 0 : (d < 30 ? 1 : 2);
        int rh = h < 28 ? 0 : (h < 30 ? 1 : 2);
        int rw = w < 14 ? 0 : (w < 15 ? 1 : 2);
        myreg = rd * 9 + rh * 3 + rw;
    }

    int tdn = lane >> 3, thn = (lane >> 1) & 3, twn = lane & 1;
    float s[32];
    #pragma unroll
    for (int m = 0; m < 32; m++) {
        float a = 0.f;
        #pragma unroll
        for (int d = 0; d < 32; d++) a += q[d] * ks[m * 33 + d];
        int idx = (tdn - (m >> 3) + 3) * 21 + (thn - ((m >> 1) & 3) + 3) * 3
                + (twn - (m & 1) + 1);
        a += bias_sh[idx * 10 + head];
        if (SHIFT) {
            int rm = __shfl_sync(0xffffffffu, myreg, m);
            if (rm != myreg) a -= 100.f;
        }
        s[m] = a;
    }

    float mx = -1e30f;
    #pragma unroll
    for (int m = 0; m < 32; m++) mx = fmaxf(mx, s[m]);
    float sum = 0.f;
    #pragma unroll
    for (int m = 0; m < 32; m++) { s[m] = __expf(s[m] - mx); sum += s[m]; }
    float inv = 1.f / sum;

    __syncwarp();
    #pragma unroll 4
    for (int m = 0; m < 32; m++) ks[m * 33 + lane] = __bfloat162float(base[m * 960 + 640 + head * 32 + lane]);
    __syncwarp();

    float o[32];
    #pragma unroll
    for (int d = 0; d < 32; d++) o[d] = 0.f;
    #pragma unroll
    for (int m = 0; m < 32; m++) {
        float p = s[m] * inv;
        #pragma unroll
        for (int d = 0; d < 32; d++) o[d] += p * ks[m * 33 + d];
    }

    __syncwarp();
    #pragma unroll
    for (int d = 0; d < 32; d++) qs[lane * 33 + d] = o[d];
    __syncwarp();
    bf16* obase = out + (size_t)win * 32 * 320 + head * 32;
    #pragma unroll 4
    for (int m = 0; m < 32; m++) obase[m * 320 + lane] = __float2bfloat16(qs[m * 33 + lane]);
}

// ---------------------------------------------------------------------------
// Host orchestration
// ---------------------------------------------------------------------------
static void run_block(bool shift, const float* const* p, bf16* wb,
                      float* t, bf16* xw, bf16* qkv, bf16* attn, bf16* mlp) {
    const float* ln1g = p[0];  const float* ln1b = p[1];
    const float* qkvb = p[3];  const float* bias = p[4];
    const float* projb = p[6];
    const float* ln2g = p[7];  const float* ln2b = p[8];
    const float* f1b = p[10];  const float* f2b = p[12];

    if (shift) k_ln<true, true ><<<16384, 256>>>(t, ln1g, ln1b, xw);
    else       k_ln<true, false><<<16384, 256>>>(t, ln1g, ln1b, xw);

    k_gemm_mma<0, false><<<dim3(15, 1024), 256>>>(xw, wb + WOFF_QKV, qkvb, qkv, 320, 960);

    if (shift) k_attn<true ><<<20480, 64>>>(qkv, bias, attn);
    else       k_attn<false><<<20480, 64>>>(qkv, bias, attn);

    if (shift) k_gemm_mma<2, true ><<<dim3(5, 1024), 256>>>(attn, wb + WOFF_PROJ, projb, t, 320, 320);
    else       k_gemm_mma<2, false><<<dim3(5, 1024), 256>>>(attn, wb + WOFF_PROJ, projb, t, 320, 320);

    k_ln<false, false><<<16384, 256>>>(t, ln2g, ln2b, xw);

    k_gemm_mma<1, false><<<dim3(20, 1024), 256>>>(xw, wb + WOFF_F1, f1b, mlp, 320, 1280);

    k_gemm_mma<3, false><<<dim3(5, 1024), 256>>>(mlp, wb + WOFF_F2, f2b, t, 1280, 320);
}

extern "C" void kernel_launch(void* const* d_in, const int* in_sizes, int n_in,
                              void* d_out, int out_size) {
    (void)in_sizes; (void)n_in; (void)out_size;
    const float* x = (const float*)d_in[0];

    void *pt, *pxw, *pqkv, *pattn, *pmlp, *pwb;
    cudaGetSymbolAddress(&pt,    g_t);
    cudaGetSymbolAddress(&pxw,   g_xw);
    cudaGetSymbolAddress(&pqkv,  g_qkv);
    cudaGetSymbolAddress(&pattn, g_attn);
    cudaGetSymbolAddress(&pmlp,  g_mlp);
    cudaGetSymbolAddress(&pwb,   g_wb);
    float* t   = (float*)pt;
    bf16* xw   = (bf16*)pxw;
    bf16* qkv  = (bf16*)pqkv;
    bf16* attn = (bf16*)pattn;
    bf16* mlp  = (bf16*)pmlp;
    bf16* wb0  = (bf16*)pwb;
    bf16* wb1  = wb0 + 1228800;

    const float* b1[13], * b2[13];
    for (int i = 0; i < 13; i++) b1[i] = (const float*)d_in[1 + i];
    for (int i = 0; i < 13; i++) b2[i] = (const float*)d_in[14 + i];

    k_wconv<<<dim3(10, 30), dim3(32, 8)>>>(b1[2],  wb0 + WOFF_QKV, 320, 960);
    k_wconv<<<dim3(10, 10), dim3(32, 8)>>>(b1[5],  wb0 + WOFF_PROJ, 320, 320);
    k_wconv<<<dim3(10, 40), dim3(32, 8)>>>(b1[9],  wb0 + WOFF_F1,  320, 1280);
    k_wconv<<<dim3(40, 10), dim3(32, 8)>>>(b1[11], wb0 + WOFF_F2, 1280, 320);
    k_wconv<<<dim3(10, 30), dim3(32, 8)>>>(b2[2],  wb1 + WOFF_QKV, 320, 960);
    k_wconv<<<dim3(10, 10), dim3(32, 8)>>>(b2[5],  wb1 + WOFF_PROJ, 320, 320);
    k_wconv<<<dim3(10, 40), dim3(32, 8)>>>(b2[9],  wb1 + WOFF_F1,  320, 1280);
    k_wconv<<<dim3(40, 10), dim3(32, 8)>>>(b2[11], wb1 + WOFF_F2, 1280, 320);

    // (B,C,L) -> (B,L,C)
    k_tin<<<dim3(L_ / 32, C_ / 32, B_), dim3(32, 8)>>>(x, t);

    run_block(false, b1, wb0, t, xw, qkv, attn, mlp);
    run_block(true,  b2, wb1, t, xw, qkv, attn, mlp);

    // (B,L,C) -> (B,C,L)
    k_tout<<<dim3(L_ / 32, C_ / 32, B_), dim3(32, 8)>>>(t, (float*)d_out);
}

// round 7
// speedup vs baseline: 3.8259x; 1.1668x over previous
#include <cuda_runtime.h>
#include <cuda_bf16.h>
#include <math.h>
#include <stdint.h>

// ---------------------------------------------------------------------------
// Problem constants
// ---------------------------------------------------------------------------
#define B_      8
#define C_      320
#define D_      32
#define H_      32
#define W_      16
#define L_      16384          // D*H*W
#define M_      131072         // B*L   (tokens)
#define QK_SCALE 0.17677669529663687f  // 1/sqrt(32)

typedef __nv_bfloat16 bf16;

// ---------------------------------------------------------------------------
// Portable tensor-core PTX helpers (sm_80+ ISA)
// ---------------------------------------------------------------------------
__device__ __forceinline__ uint32_t smem_to_u32(const void* p) {
    uint32_t a;
    asm("{ .reg .u64 t; cvta.to.shared.u64 t, %1; cvt.u32.u64 %0, t; }" : "=r"(a) : "l"(p));
    return a;
}
__device__ __forceinline__ void cp_async16(uint32_t dst, const void* src) {
    asm volatile("cp.async.cg.shared.global [%0], [%1], 16;" :: "r"(dst), "l"(src));
}
#define CP_COMMIT() asm volatile("cp.async.commit_group;" ::: "memory")
#define CP_WAIT1()  asm volatile("cp.async.wait_group 1;" ::: "memory")
#define CP_WAIT0()  asm volatile("cp.async.wait_group 0;" ::: "memory")

#define LDSM_X4(r0, r1, r2, r3, a) \
    asm volatile("ldmatrix.sync.aligned.m8n8.x4.shared.b16 {%0,%1,%2,%3}, [%4];" \
                 : "=r"(r0), "=r"(r1), "=r"(r2), "=r"(r3) : "r"(a))
#define LDSM_X2(r0, r1, a) \
    asm volatile("ldmatrix.sync.aligned.m8n8.x2.shared.b16 {%0,%1}, [%2];" \
                 : "=r"(r0), "=r"(r1) : "r"(a))

__device__ __forceinline__ void mma_16816(float* c, const uint32_t* a, const uint32_t* b) {
    asm volatile(
        "mma.sync.aligned.m16n8k16.row.col.f32.bf16.bf16.f32 "
        "{%0,%1,%2,%3}, {%4,%5,%6,%7}, {%8,%9}, {%0,%1,%2,%3};"
        : "+f"(c[0]), "+f"(c[1]), "+f"(c[2]), "+f"(c[3])
        : "r"(a[0]), "r"(a[1]), "r"(a[2]), "r"(a[3]), "r"(b[0]), "r"(b[1]));
}

// ---------------------------------------------------------------------------
// Scratch (static device globals)
// ---------------------------------------------------------------------------
__device__ float g_t   [(size_t)M_ * C_];      // residual stream fp32 (B,L,C)
__device__ bf16  g_xw  [(size_t)M_ * C_];      // LN output bf16
__device__ bf16  g_qkv [(size_t)M_ * 960];     // qkv bf16, windowed rows
__device__ bf16  g_attn[(size_t)M_ * C_];      // attention out bf16, windowed rows
__device__ bf16  g_mlp [(size_t)M_ * 1280];    // gelu(f1) out bf16
__device__ bf16  g_wb[2][1228800];             // [N,K] bf16 weights per block
#define WOFF_QKV 0
#define WOFF_PROJ 307200
#define WOFF_F1 409600
#define WOFF_F2 819200

// ---------------------------------------------------------------------------
// Window geometry
// ---------------------------------------------------------------------------
__device__ __forceinline__ int win_src_row(int r, bool shift) {
    int b   = r >> 14;
    int rem = r & 16383;
    int wi  = rem >> 5;
    int n   = rem & 31;
    int d = ((wi >> 6) << 2)        + (n >> 3);
    int h = (((wi >> 3) & 7) << 2)  + ((n >> 1) & 3);
    int w = ((wi & 7) << 1)         + (n & 1);
    if (shift) { d = (d + 2) & 31; h = (h + 2) & 31; w = (w + 1) & 15; }
    return (b << 14) + (d << 9) + (h << 4) + w;
}

// ---------------------------------------------------------------------------
// Transposes (fp32)
// ---------------------------------------------------------------------------
__global__ void k_tin(const float* __restrict__ x, float* __restrict__ t) {
    __shared__ float tile[32][33];
    int b = blockIdx.z, l0 = blockIdx.x * 32, c0 = blockIdx.y * 32;
    int tx = threadIdx.x, ty = threadIdx.y;
    #pragma unroll
    for (int i = ty; i < 32; i += 8)
        tile[i][tx] = x[((size_t)(b * C_ + c0 + i)) * L_ + l0 + tx];
    __syncthreads();
    #pragma unroll
    for (int i = ty; i < 32; i += 8)
        t[((size_t)(b * L_ + l0 + i)) * C_ + c0 + tx] = tile[tx][i];
}
__global__ void k_tout(const float* __restrict__ t, float* __restrict__ o) {
    __shared__ float tile[32][33];
    int b = blockIdx.z, l0 = blockIdx.x * 32, c0 = blockIdx.y * 32;
    int tx = threadIdx.x, ty = threadIdx.y;
    #pragma unroll
    for (int i = ty; i < 32; i += 8)
        tile[i][tx] = t[((size_t)(b * L_ + l0 + i)) * C_ + c0 + tx];
    __syncthreads();
    #pragma unroll
    for (int i = ty; i < 32; i += 8)
        o[((size_t)(b * C_ + c0 + i)) * L_ + l0 + tx] = tile[tx][i];
}

// ---------------------------------------------------------------------------
// Weight convert + transpose: W[K,N] fp32 -> out[N,K] bf16
// ---------------------------------------------------------------------------
__global__ void k_wconv(const float* __restrict__ Wm, bf16* __restrict__ out, int K, int N) {
    __shared__ float tile[32][33];
    int k0 = blockIdx.x * 32, n0 = blockIdx.y * 32;
    int tx = threadIdx.x, ty = threadIdx.y;
    #pragma unroll
    for (int i = ty; i < 32; i += 8)
        tile[i][tx] = Wm[(size_t)(k0 + i) * N + n0 + tx];
    __syncthreads();
    #pragma unroll
    for (int i = ty; i < 32; i += 8)
        out[(size_t)(n0 + i) * K + k0 + tx] = __float2bfloat16(tile[tx][i]);
}

// ---------------------------------------------------------------------------
// LayerNorm (one warp per token) -> bf16, optional windowed gather
// ---------------------------------------------------------------------------
template<bool WIN, bool SHIFT>
__global__ void k_ln(const float* __restrict__ t, const float* __restrict__ gam,
                     const float* __restrict__ bet, bf16* __restrict__ out) {
    int warp = (blockIdx.x * blockDim.x + threadIdx.x) >> 5;
    int lane = threadIdx.x & 31;
    if (warp >= M_) return;
    int src = WIN ? win_src_row(warp, SHIFT) : warp;
    const float* row = t + (size_t)src * C_;
    float v[10]; float s = 0.f;
    #pragma unroll
    for (int i = 0; i < 10; i++) { v[i] = row[lane + 32 * i]; s += v[i]; }
    #pragma unroll
    for (int o = 16; o; o >>= 1) s += __shfl_xor_sync(0xffffffffu, s, o);
    float mu = s * (1.f / C_); float var = 0.f;
    #pragma unroll
    for (int i = 0; i < 10; i++) { float d = v[i] - mu; var += d * d; }
    #pragma unroll
    for (int o = 16; o; o >>= 1) var += __shfl_xor_sync(0xffffffffu, var, o);
    float inv = rsqrtf(var * (1.f / C_) + 1e-5f);
    bf16* orow = out + (size_t)warp * C_;
    #pragma unroll
    for (int i = 0; i < 10; i++) {
        int c = lane + 32 * i;
        orow[c] = __float2bfloat16((v[i] - mu) * inv * gam[c] + bet[c]);
    }
}

// ---------------------------------------------------------------------------
// HMMA GEMM: Out[M_,Nn] = A[M_,K](bf16) @ Wt[Nn,K]^T(bf16) (+bias, epilogue)
// BM=128, BN=64, BK=32.  128 threads (4 warps, 2x2), warp tile 64x32.
// 3-stage cp.async pipeline; 40-bf16 padded rows (conflict-free ldmatrix).
// STATIC smem 46080B (<48KB: no opt-in, no host attribute APIs).
// EPI: 0 = bf16 store (+bias)
//      1 = bf16 store gelu(v+bias)
//      2 = fp32 += into Out at window-reversed row (Nn==320)
//      3 = fp32 += into Out plain row (Nn==320)
// ---------------------------------------------------------------------------
#define LDA 40                       // padded row stride (bf16 elems)
#define G_STAGES 3
#define G_ASZ (128 * LDA)            // A stage elems = 5120
#define G_BSZ (64 * LDA)             // B stage elems = 2560

template<int EPI, bool SHIFT>
__global__ __launch_bounds__(128)
void k_gemm_mma(const bf16* __restrict__ A, const bf16* __restrict__ Wt,
                const float* __restrict__ bias, void* __restrict__ OutP,
                int K, int Nn) {
    __shared__ __align__(16) bf16 Asm[G_STAGES][G_ASZ];
    __shared__ __align__(16) bf16 Bsm[G_STAGES][G_BSZ];

    const int tid = threadIdx.x, lane = tid & 31, wid = tid >> 5;
    const int wm = wid & 1, wn = wid >> 1;           // 2 x 2 warp grid
    const int m0 = blockIdx.y * 128, n0 = blockIdx.x * 64;

    uint32_t sA[G_STAGES], sB[G_STAGES];
    #pragma unroll
    for (int s = 0; s < G_STAGES; s++) {
        sA[s] = smem_to_u32(Asm[s]);
        sB[s] = smem_to_u32(Bsm[s]);
    }

    float acc[4][4][4];
    #pragma unroll
    for (int i = 0; i < 4; i++)
        #pragma unroll
        for (int j = 0; j < 4; j++)
            #pragma unroll
            for (int k = 0; k < 4; k++) acc[i][j][k] = 0.f;

    const int NC = K >> 5;   // chunks of 32

    auto issue = [&](int kc, int buf) {
        const bf16* Ag = A + (size_t)m0 * K + kc * 32;
        #pragma unroll
        for (int i = 0; i < 4; i++) {
            int v = tid + i * 128;
            int row = v >> 2, c8 = (v & 3) * 8;
            cp_async16(sA[buf] + (uint32_t)(row * LDA + c8) * 2,
                       Ag + (size_t)row * K + c8);
        }
        const bf16* Bg = Wt + (size_t)n0 * K + kc * 32;
        #pragma unroll
        for (int i = 0; i < 2; i++) {
            int v = tid + i * 128;
            int row = v >> 2, c8 = (v & 3) * 8;
            cp_async16(sB[buf] + (uint32_t)(row * LDA + c8) * 2,
                       Bg + (size_t)row * K + c8);
        }
    };

    issue(0, 0); CP_COMMIT();
    issue(1, 1); CP_COMMIT();

    for (int kc = 0; kc < NC; kc++) {
        int buf = kc % G_STAGES;
        if (kc + 2 < NC) CP_WAIT1(); else CP_WAIT0();
        __syncthreads();

        #pragma unroll
        for (int ks = 0; ks < 2; ks++) {
            int k0 = ks * 16;
            uint32_t afr[4][4];
            #pragma unroll
            for (int mt = 0; mt < 4; mt++) {
                uint32_t addr = sA[buf] +
                    (uint32_t)(((wm * 64 + mt * 16 + (lane & 15)) * LDA)
                               + k0 + ((lane >> 4) * 8)) * 2;
                LDSM_X4(afr[mt][0], afr[mt][1], afr[mt][2], afr[mt][3], addr);
            }
            uint32_t bfr[4][2];
            #pragma unroll
            for (int nt = 0; nt < 4; nt++) {
                uint32_t addr = sB[buf] +
                    (uint32_t)(((wn * 32 + nt * 8 + (lane & 7)) * LDA)
                               + k0 + (((lane & 15) >> 3) * 8)) * 2;
                LDSM_X2(bfr[nt][0], bfr[nt][1], addr);
            }
            #pragma unroll
            for (int mt = 0; mt < 4; mt++)
                #pragma unroll
                for (int nt = 0; nt < 4; nt++)
                    mma_16816(acc[mt][nt], afr[mt], bfr[nt]);
        }
        __syncthreads();
        if (kc + 2 < NC) { issue(kc + 2, (kc + 2) % G_STAGES); CP_COMMIT(); }
    }

    // Epilogue: c-frag regs {0,1}->row lane/4, {2,3}->row lane/4+8; cols (lane%4)*2+{0,1}
    const int qr = lane >> 2, qc = (lane & 3) * 2;
    #pragma unroll
    for (int nt = 0; nt < 4; nt++) {
        int gn = n0 + wn * 32 + nt * 8 + qc;
        float b0 = bias[gn], b1 = bias[gn + 1];
        #pragma unroll
        for (int mt = 0; mt < 4; mt++) {
            int gmA = m0 + wm * 64 + mt * 16 + qr;
            float v0 = acc[mt][nt][0] + b0;
            float v1 = acc[mt][nt][1] + b1;
            float v2 = acc[mt][nt][2] + b0;
            float v3 = acc[mt][nt][3] + b1;
            if (EPI == 1) {
                v0 = 0.5f * v0 * (1.f + erff(v0 * 0.70710678118654752f));
                v1 = 0.5f * v1 * (1.f + erff(v1 * 0.70710678118654752f));
                v2 = 0.5f * v2 * (1.f + erff(v2 * 0.70710678118654752f));
                v3 = 0.5f * v3 * (1.f + erff(v3 * 0.70710678118654752f));
            }
            if (EPI == 0 || EPI == 1) {
                bf16* Ob = (bf16*)OutP;
                __nv_bfloat162* p0 = (__nv_bfloat162*)(Ob + (size_t)gmA * Nn + gn);
                *p0 = __floats2bfloat162_rn(v0, v1);
                __nv_bfloat162* p1 = (__nv_bfloat162*)(Ob + (size_t)(gmA + 8) * Nn + gn);
                *p1 = __floats2bfloat162_rn(v2, v3);
            } else {
                float* Of = (float*)OutP;
                int r0 = (EPI == 2) ? win_src_row(gmA, SHIFT) : gmA;
                int r1 = (EPI == 2) ? win_src_row(gmA + 8, SHIFT) : (gmA + 8);
                float* p0 = Of + (size_t)r0 * 320 + gn;
                float* p1 = Of + (size_t)r1 * 320 + gn;
                p0[0] += v0; p0[1] += v1;
                p1[0] += v2; p1[1] += v3;
            }
        }
    }
}

// ---------------------------------------------------------------------------
// Windowed attention: one warp per (window, head), bf16 I/O
// ---------------------------------------------------------------------------
template<bool SHIFT>
__global__ void k_attn(const bf16* __restrict__ qkv,
                       const float* __restrict__ biasTab,
                       bf16* __restrict__ out) {
    __shared__ float bias_sh[147 * 10];
    __shared__ float bufA[2][32 * 33];
    __shared__ float bufB[2][32 * 33];
    int tid = threadIdx.x, lane = tid & 31, wrp = tid >> 5;
    for (int i = tid; i < 1470; i += 64) bias_sh[i] = biasTab[i];
    __syncthreads();

    int g = blockIdx.x * 2 + wrp;
    int win = g / 10;
    int head = g - win * 10;
    const bf16* base = qkv + (size_t)win * 32 * 960;
    float* qs = bufA[wrp];
    float* ks = bufB[wrp];

    #pragma unroll 4
    for (int m = 0; m < 32; m++) ks[m * 33 + lane] = __bfloat162float(base[m * 960 + 320 + head * 32 + lane]);
    #pragma unroll 4
    for (int m = 0; m < 32; m++) qs[m * 33 + lane] = __bfloat162float(base[m * 960 +       head * 32 + lane]);
    __syncwarp();

    float q[32];
    #pragma unroll
    for (int d = 0; d < 32; d++) q[d] = qs[lane * 33 + d] * QK_SCALE;

    int myreg = 0;
    if (SHIFT) {
        int wi = win & 511;
        int d = ((wi >> 6) << 2)       + (lane >> 3);
        int h = (((wi >> 3) & 7) << 2) + ((lane >> 1) & 3);
        int w = ((wi & 7) << 1)        + (lane & 1);
        int rd = d < 28 ? 0 : (d < 30 ? 1 : 2);
        int rh = h < 28 ? 0 : (h < 30 ? 1 : 2);
        int rw = w < 14 ? 0 : (w < 15 ? 1 : 2);
        myreg = rd * 9 + rh * 3 + rw;
    }

    int tdn = lane >> 3, thn = (lane >> 1) & 3, twn = lane & 1;
    float s[32];
    #pragma unroll
    for (int m = 0; m < 32; m++) {
        float a = 0.f;
        #pragma unroll
        for (int d = 0; d < 32; d++) a += q[d] * ks[m * 33 + d];
        int idx = (tdn - (m >> 3) + 3) * 21 + (thn - ((m >> 1) & 3) + 3) * 3
                + (twn - (m & 1) + 1);
        a += bias_sh[idx * 10 + head];
        if (SHIFT) {
            int rm = __shfl_sync(0xffffffffu, myreg, m);
            if (rm != myreg) a -= 100.f;
        }
        s[m] = a;
    }

    float mx = -1e30f;
    #pragma unroll
    for (int m = 0; m < 32; m++) mx = fmaxf(mx, s[m]);
    float sum = 0.f;
    #pragma unroll
    for (int m = 0; m < 32; m++) { s[m] = __expf(s[m] - mx); sum += s[m]; }
    float inv = 1.f / sum;

    __syncwarp();
    #pragma unroll 4
    for (int m = 0; m < 32; m++) ks[m * 33 + lane] = __bfloat162float(base[m * 960 + 640 + head * 32 + lane]);
    __syncwarp();

    float o[32];
    #pragma unroll
    for (int d = 0; d < 32; d++) o[d] = 0.f;
    #pragma unroll
    for (int m = 0; m < 32; m++) {
        float p = s[m] * inv;
        #pragma unroll
        for (int d = 0; d < 32; d++) o[d] += p * ks[m * 33 + d];
    }

    __syncwarp();
    #pragma unroll
    for (int d = 0; d < 32; d++) qs[lane * 33 + d] = o[d];
    __syncwarp();
    bf16* obase = out + (size_t)win * 32 * 320 + head * 32;
    #pragma unroll 4
    for (int m = 0; m < 32; m++) obase[m * 320 + lane] = __float2bfloat16(qs[m * 33 + lane]);
}

// ---------------------------------------------------------------------------
// Host orchestration
// ---------------------------------------------------------------------------
static void run_block(bool shift, const float* const* p, bf16* wb,
                      float* t, bf16* xw, bf16* qkv, bf16* attn, bf16* mlp) {
    const float* ln1g = p[0];  const float* ln1b = p[1];
    const float* qkvb = p[3];  const float* bias = p[4];
    const float* projb = p[6];
    const float* ln2g = p[7];  const float* ln2b = p[8];
    const float* f1b = p[10];  const float* f2b = p[12];

    if (shift) k_ln<true, true ><<<16384, 256>>>(t, ln1g, ln1b, xw);
    else       k_ln<true, false><<<16384, 256>>>(t, ln1g, ln1b, xw);

    k_gemm_mma<0, false><<<dim3(15, 1024), 128>>>(xw, wb + WOFF_QKV, qkvb, qkv, 320, 960);

    if (shift) k_attn<true ><<<20480, 64>>>(qkv, bias, attn);
    else       k_attn<false><<<20480, 64>>>(qkv, bias, attn);

    if (shift) k_gemm_mma<2, true ><<<dim3(5, 1024), 128>>>(attn, wb + WOFF_PROJ, projb, t, 320, 320);
    else       k_gemm_mma<2, false><<<dim3(5, 1024), 128>>>(attn, wb + WOFF_PROJ, projb, t, 320, 320);

    k_ln<false, false><<<16384, 256>>>(t, ln2g, ln2b, xw);

    k_gemm_mma<1, false><<<dim3(20, 1024), 128>>>(xw, wb + WOFF_F1, f1b, mlp, 320, 1280);

    k_gemm_mma<3, false><<<dim3(5, 1024), 128>>>(mlp, wb + WOFF_F2, f2b, t, 1280, 320);
}

extern "C" void kernel_launch(void* const* d_in, const int* in_sizes, int n_in,
                              void* d_out, int out_size) {
    (void)in_sizes; (void)n_in; (void)out_size;
    const float* x = (const float*)d_in[0];

    void *pt, *pxw, *pqkv, *pattn, *pmlp, *pwb;
    cudaGetSymbolAddress(&pt,    g_t);
    cudaGetSymbolAddress(&pxw,   g_xw);
    cudaGetSymbolAddress(&pqkv,  g_qkv);
    cudaGetSymbolAddress(&pattn, g_attn);
    cudaGetSymbolAddress(&pmlp,  g_mlp);
    cudaGetSymbolAddress(&pwb,   g_wb);
    float* t   = (float*)pt;
    bf16* xw   = (bf16*)pxw;
    bf16* qkv  = (bf16*)pqkv;
    bf16* attn = (bf16*)pattn;
    bf16* mlp  = (bf16*)pmlp;
    bf16* wb0  = (bf16*)pwb;
    bf16* wb1  = wb0 + 1228800;

    const float* b1[13], * b2[13];
    for (int i = 0; i < 13; i++) b1[i] = (const float*)d_in[1 + i];
    for (int i = 0; i < 13; i++) b2[i] = (const float*)d_in[14 + i];

    k_wconv<<<dim3(10, 30), dim3(32, 8)>>>(b1[2],  wb0 + WOFF_QKV, 320, 960);
    k_wconv<<<dim3(10, 10), dim3(32, 8)>>>(b1[5],  wb0 + WOFF_PROJ, 320, 320);
    k_wconv<<<dim3(10, 40), dim3(32, 8)>>>(b1[9],  wb0 + WOFF_F1,  320, 1280);
    k_wconv<<<dim3(40, 10), dim3(32, 8)>>>(b1[11], wb0 + WOFF_F2, 1280, 320);
    k_wconv<<<dim3(10, 30), dim3(32, 8)>>>(b2[2],  wb1 + WOFF_QKV, 320, 960);
    k_wconv<<<dim3(10, 10), dim3(32, 8)>>>(b2[5],  wb1 + WOFF_PROJ, 320, 320);
    k_wconv<<<dim3(10, 40), dim3(32, 8)>>>(b2[9],  wb1 + WOFF_F1,  320, 1280);
    k_wconv<<<dim3(40, 10), dim3(32, 8)>>>(b2[11], wb1 + WOFF_F2, 1280, 320);

    // (B,C,L) -> (B,L,C)
    k_tin<<<dim3(L_ / 32, C_ / 32, B_), dim3(32, 8)>>>(x, t);

    run_block(false, b1, wb0, t, xw, qkv, attn, mlp);
    run_block(true,  b2, wb1, t, xw, qkv, attn, mlp);

    // (B,L,C) -> (B,C,L)
    k_tout<<<dim3(L_ / 32, C_ / 32, B_), dim3(32, 8)>>>(t, (float*)d_out);
}

// round 9
// speedup vs baseline: 4.2073x; 1.0997x over previous
#include <cuda_runtime.h>
#include <cuda_bf16.h>
#include <math.h>
#include <stdint.h>

// ---------------------------------------------------------------------------
// Problem constants
// ---------------------------------------------------------------------------
#define B_      8
#define C_      320
#define D_      32
#define H_      32
#define W_      16
#define L_      16384          // D*H*W
#define M_      131072         // B*L   (tokens)
#define QK_SCALE 0.17677669529663687f  // 1/sqrt(32)

typedef __nv_bfloat16 bf16;

// ---------------------------------------------------------------------------
// Portable tensor-core PTX helpers (sm_80+ ISA)
// ---------------------------------------------------------------------------
__device__ __forceinline__ uint32_t smem_to_u32(const void* p) {
    uint32_t a;
    asm("{ .reg .u64 t; cvta.to.shared.u64 t, %1; cvt.u32.u64 %0, t; }" : "=r"(a) : "l"(p));
    return a;
}
__device__ __forceinline__ void cp_async16(uint32_t dst, const void* src) {
    asm volatile("cp.async.cg.shared.global [%0], [%1], 16;" :: "r"(dst), "l"(src));
}
#define CP_COMMIT() asm volatile("cp.async.commit_group;" ::: "memory")
#define CP_WAIT1()  asm volatile("cp.async.wait_group 1;" ::: "memory")
#define CP_WAIT0()  asm volatile("cp.async.wait_group 0;" ::: "memory")

#define LDSM_X4(r0, r1, r2, r3, a) \
    asm volatile("ldmatrix.sync.aligned.m8n8.x4.shared.b16 {%0,%1,%2,%3}, [%4];" \
                 : "=r"(r0), "=r"(r1), "=r"(r2), "=r"(r3) : "r"(a))
#define LDSM_X4_TRANS(r0, r1, r2, r3, a) \
    asm volatile("ldmatrix.sync.aligned.m8n8.x4.trans.shared.b16 {%0,%1,%2,%3}, [%4];" \
                 : "=r"(r0), "=r"(r1), "=r"(r2), "=r"(r3) : "r"(a))

__device__ __forceinline__ void mma_16816(float* c, const uint32_t* a, const uint32_t* b) {
    asm volatile(
        "mma.sync.aligned.m16n8k16.row.col.f32.bf16.bf16.f32 "
        "{%0,%1,%2,%3}, {%4,%5,%6,%7}, {%8,%9}, {%0,%1,%2,%3};"
        : "+f"(c[0]), "+f"(c[1]), "+f"(c[2]), "+f"(c[3])
        : "r"(a[0]), "r"(a[1]), "r"(a[2]), "r"(a[3]), "r"(b[0]), "r"(b[1]));
}
__device__ __forceinline__ uint32_t packbf2(float lo, float hi) {
    __nv_bfloat162 v = __floats2bfloat162_rn(lo, hi);
    return *(uint32_t*)&v;
}

// ---------------------------------------------------------------------------
// Scratch (static device globals)
// ---------------------------------------------------------------------------
__device__ float g_t   [(size_t)M_ * C_];      // residual stream fp32 (B,L,C)
__device__ bf16  g_xw  [(size_t)M_ * C_];      // LN output bf16
__device__ bf16  g_qkv [(size_t)M_ * 960];     // qkv bf16, windowed rows
__device__ bf16  g_attn[(size_t)M_ * C_];      // attention out bf16, windowed rows
__device__ bf16  g_mlp [(size_t)M_ * 1280];    // gelu(f1) out bf16
__device__ bf16  g_wb[2][1228800];             // [N,K] bf16 weights per block
#define WOFF_QKV 0
#define WOFF_PROJ 307200
#define WOFF_F1 409600
#define WOFF_F2 819200

// ---------------------------------------------------------------------------
// Window geometry
// ---------------------------------------------------------------------------
__device__ __forceinline__ int win_src_row(int r, bool shift) {
    int b   = r >> 14;
    int rem = r & 16383;
    int wi  = rem >> 5;
    int n   = rem & 31;
    int d = ((wi >> 6) << 2)        + (n >> 3);
    int h = (((wi >> 3) & 7) << 2)  + ((n >> 1) & 3);
    int w = ((wi & 7) << 1)         + (n & 1);
    if (shift) { d = (d + 2) & 31; h = (h + 2) & 31; w = (w + 1) & 15; }
    return (b << 14) + (d << 9) + (h << 4) + w;
}

// ---------------------------------------------------------------------------
// Transposes (fp32)
// ---------------------------------------------------------------------------
__global__ void k_tin(const float* __restrict__ x, float* __restrict__ t) {
    __shared__ float tile[32][33];
    int b = blockIdx.z, l0 = blockIdx.x * 32, c0 = blockIdx.y * 32;
    int tx = threadIdx.x, ty = threadIdx.y;
    #pragma unroll
    for (int i = ty; i < 32; i += 8)
        tile[i][tx] = x[((size_t)(b * C_ + c0 + i)) * L_ + l0 + tx];
    __syncthreads();
    #pragma unroll
    for (int i = ty; i < 32; i += 8)
        t[((size_t)(b * L_ + l0 + i)) * C_ + c0 + tx] = tile[tx][i];
}
__global__ void k_tout(const float* __restrict__ t, float* __restrict__ o) {
    __shared__ float tile[32][33];
    int b = blockIdx.z, l0 = blockIdx.x * 32, c0 = blockIdx.y * 32;
    int tx = threadIdx.x, ty = threadIdx.y;
    #pragma unroll
    for (int i = ty; i < 32; i += 8)
        tile[i][tx] = t[((size_t)(b * L_ + l0 + i)) * C_ + c0 + tx];
    __syncthreads();
    #pragma unroll
    for (int i = ty; i < 32; i += 8)
        o[((size_t)(b * C_ + c0 + i)) * L_ + l0 + tx] = tile[tx][i];
}

// ---------------------------------------------------------------------------
// Weight convert + transpose: W[K,N] fp32 -> out[N,K] bf16
// ---------------------------------------------------------------------------
__global__ void k_wconv(const float* __restrict__ Wm, bf16* __restrict__ out, int K, int N) {
    __shared__ float tile[32][33];
    int k0 = blockIdx.x * 32, n0 = blockIdx.y * 32;
    int tx = threadIdx.x, ty = threadIdx.y;
    #pragma unroll
    for (int i = ty; i < 32; i += 8)
        tile[i][tx] = Wm[(size_t)(k0 + i) * N + n0 + tx];
    __syncthreads();
    #pragma unroll
    for (int i = ty; i < 32; i += 8)
        out[(size_t)(n0 + i) * K + k0 + tx] = __float2bfloat16(tile[tx][i]);
}

// ---------------------------------------------------------------------------
// LayerNorm (one warp per token) -> bf16, optional windowed gather
// ---------------------------------------------------------------------------
template<bool WIN, bool SHIFT>
__global__ void k_ln(const float* __restrict__ t, const float* __restrict__ gam,
                     const float* __restrict__ bet, bf16* __restrict__ out) {
    int warp = (blockIdx.x * blockDim.x + threadIdx.x) >> 5;
    int lane = threadIdx.x & 31;
    if (warp >= M_) return;
    int src = WIN ? win_src_row(warp, SHIFT) : warp;
    const float* row = t + (size_t)src * C_;
    float v[10]; float s = 0.f;
    #pragma unroll
    for (int i = 0; i < 10; i++) { v[i] = row[lane + 32 * i]; s += v[i]; }
    #pragma unroll
    for (int o = 16; o; o >>= 1) s += __shfl_xor_sync(0xffffffffu, s, o);
    float mu = s * (1.f / C_); float var = 0.f;
    #pragma unroll
    for (int i = 0; i < 10; i++) { float d = v[i] - mu; var += d * d; }
    #pragma unroll
    for (int o = 16; o; o >>= 1) var += __shfl_xor_sync(0xffffffffu, var, o);
    float inv = rsqrtf(var * (1.f / C_) + 1e-5f);
    bf16* orow = out + (size_t)warp * C_;
    #pragma unroll
    for (int i = 0; i < 10; i++) {
        int c = lane + 32 * i;
        orow[c] = __float2bfloat16((v[i] - mu) * inv * gam[c] + bet[c]);
    }
}

// ---------------------------------------------------------------------------
// HMMA GEMM: BM=128, BN=64, BK=32, 128 threads (2x2 warps of 64x32),
// 3-stage cp.async, static smem 46080B.  B-frags via paired ldmatrix.x4.
// EPI: 0 bf16 (+bias) | 1 bf16 gelu | 2 fp32 += win-reversed | 3 fp32 += plain
// ---------------------------------------------------------------------------
#define LDA 40
#define G_STAGES 3
#define G_ASZ (128 * LDA)
#define G_BSZ (64 * LDA)

template<int EPI, bool SHIFT>
__global__ __launch_bounds__(128)
void k_gemm_mma(const bf16* __restrict__ A, const bf16* __restrict__ Wt,
                const float* __restrict__ bias, void* __restrict__ OutP,
                int K, int Nn) {
    __shared__ __align__(16) bf16 Asm[G_STAGES][G_ASZ];
    __shared__ __align__(16) bf16 Bsm[G_STAGES][G_BSZ];

    const int tid = threadIdx.x, lane = tid & 31, wid = tid >> 5;
    const int wm = wid & 1, wn = wid >> 1;
    const int m0 = blockIdx.y * 128, n0 = blockIdx.x * 64;

    uint32_t sA[G_STAGES], sB[G_STAGES];
    #pragma unroll
    for (int s = 0; s < G_STAGES; s++) {
        sA[s] = smem_to_u32(Asm[s]);
        sB[s] = smem_to_u32(Bsm[s]);
    }

    float acc[4][4][4];
    #pragma unroll
    for (int i = 0; i < 4; i++)
        #pragma unroll
        for (int j = 0; j < 4; j++)
            #pragma unroll
            for (int k = 0; k < 4; k++) acc[i][j][k] = 0.f;

    const int NC = K >> 5;

    auto issue = [&](int kc, int buf) {
        const bf16* Ag = A + (size_t)m0 * K + kc * 32;
        #pragma unroll
        for (int i = 0; i < 4; i++) {
            int v = tid + i * 128;
            int row = v >> 2, c8 = (v & 3) * 8;
            cp_async16(sA[buf] + (uint32_t)(row * LDA + c8) * 2,
                       Ag + (size_t)row * K + c8);
        }
        const bf16* Bg = Wt + (size_t)n0 * K + kc * 32;
        #pragma unroll
        for (int i = 0; i < 2; i++) {
            int v = tid + i * 128;
            int row = v >> 2, c8 = (v & 3) * 8;
            cp_async16(sB[buf] + (uint32_t)(row * LDA + c8) * 2,
                       Bg + (size_t)row * K + c8);
        }
    };

    issue(0, 0); CP_COMMIT();
    issue(1, 1); CP_COMMIT();

    for (int kc = 0; kc < NC; kc++) {
        int buf = kc % G_STAGES;
        if (kc + 2 < NC) CP_WAIT1(); else CP_WAIT0();
        __syncthreads();

        #pragma unroll
        for (int ks = 0; ks < 2; ks++) {
            int k0 = ks * 16;
            uint32_t afr[4][4];
            #pragma unroll
            for (int mt = 0; mt < 4; mt++) {
                uint32_t addr = sA[buf] +
                    (uint32_t)(((wm * 64 + mt * 16 + (lane & 15)) * LDA)
                               + k0 + ((lane >> 4) * 8)) * 2;
                LDSM_X4(afr[mt][0], afr[mt][1], afr[mt][2], afr[mt][3], addr);
            }
            // B frags: 2 x ldmatrix.x4, each covering an n-tile pair
            uint32_t bfr[4][2];
            #pragma unroll
            for (int p = 0; p < 2; p++) {
                uint32_t addr = sB[buf] +
                    (uint32_t)(((wn * 32 + p * 16 + ((lane >> 4) & 1) * 8 + (lane & 7)) * LDA)
                               + k0 + ((lane >> 3) & 1) * 8) * 2;
                uint32_t r0, r1, r2, r3;
                LDSM_X4(r0, r1, r2, r3, addr);
                bfr[2 * p][0] = r0;     bfr[2 * p][1] = r1;
                bfr[2 * p + 1][0] = r2; bfr[2 * p + 1][1] = r3;
            }
            #pragma unroll
            for (int mt = 0; mt < 4; mt++)
                #pragma unroll
                for (int nt = 0; nt < 4; nt++)
                    mma_16816(acc[mt][nt], afr[mt], bfr[nt]);
        }
        __syncthreads();
        if (kc + 2 < NC) { issue(kc + 2, (kc + 2) % G_STAGES); CP_COMMIT(); }
    }

    const int qr = lane >> 2, qc = (lane & 3) * 2;
    #pragma unroll
    for (int nt = 0; nt < 4; nt++) {
        int gn = n0 + wn * 32 + nt * 8 + qc;
        float b0 = bias[gn], b1 = bias[gn + 1];
        #pragma unroll
        for (int mt = 0; mt < 4; mt++) {
            int gmA = m0 + wm * 64 + mt * 16 + qr;
            float v0 = acc[mt][nt][0] + b0;
            float v1 = acc[mt][nt][1] + b1;
            float v2 = acc[mt][nt][2] + b0;
            float v3 = acc[mt][nt][3] + b1;
            if (EPI == 1) {
                v0 = 0.5f * v0 * (1.f + erff(v0 * 0.70710678118654752f));
                v1 = 0.5f * v1 * (1.f + erff(v1 * 0.70710678118654752f));
                v2 = 0.5f * v2 * (1.f + erff(v2 * 0.70710678118654752f));
                v3 = 0.5f * v3 * (1.f + erff(v3 * 0.70710678118654752f));
            }
            if (EPI == 0 || EPI == 1) {
                bf16* Ob = (bf16*)OutP;
                *(__nv_bfloat162*)(Ob + (size_t)gmA * Nn + gn) = __floats2bfloat162_rn(v0, v1);
                *(__nv_bfloat162*)(Ob + (size_t)(gmA + 8) * Nn + gn) = __floats2bfloat162_rn(v2, v3);
            } else {
                float* Of = (float*)OutP;
                int r0 = (EPI == 2) ? win_src_row(gmA, SHIFT) : gmA;
                int r1 = (EPI == 2) ? win_src_row(gmA + 8, SHIFT) : (gmA + 8);
                float* p0 = Of + (size_t)r0 * 320 + gn;
                float* p1 = Of + (size_t)r1 * 320 + gn;
                p0[0] += v0; p0[1] += v1;
                p1[0] += v2; p1[1] += v3;
            }
        }
    }
}

// ---------------------------------------------------------------------------
// Warp-mma windowed attention: one warp per (window, head); 4 warps/block
// (de-risked from 8: smem 26.4KB, lower per-block register pressure).
// S = Q@K^T via m16n8k16; softmax in c-frags; P repacked to a-frags; O = P@V
// with V b-frags via ldmatrix.x4.trans.
// ---------------------------------------------------------------------------
#define ATT_LD 40

template<bool SHIFT>
__global__ __launch_bounds__(128)
void k_attn(const bf16* __restrict__ qkv,
            const float* __restrict__ biasTab,
            bf16* __restrict__ out) {
    __shared__ float bias_sh[1470];
    __shared__ __align__(16) bf16 kbuf[4][32 * ATT_LD];
    __shared__ __align__(16) bf16 qvbuf[4][32 * ATT_LD];   // q, then v

    int tid = threadIdx.x, lane = tid & 31, wrp = tid >> 5;
    for (int i = tid; i < 1470; i += 128) bias_sh[i] = biasTab[i];
    __syncthreads();

    int gwh = blockIdx.x * 4 + wrp;
    int win = gwh / 10;
    int head = gwh - win * 10;
    const bf16* base = qkv + (size_t)win * 32 * 960;
    bf16* ks = kbuf[wrp];
    bf16* qs = qvbuf[wrp];
    uint32_t ksu = smem_to_u32(ks), qsu = smem_to_u32(qs);

    // stage K (rows=tokens) and Q (scaled)
    #pragma unroll 4
    for (int m = 0; m < 32; m++) ks[m * ATT_LD + lane] = base[m * 960 + 320 + head * 32 + lane];
    #pragma unroll 4
    for (int m = 0; m < 32; m++)
        qs[m * ATT_LD + lane] =
            __float2bfloat16(__bfloat162float(base[m * 960 + head * 32 + lane]) * QK_SCALE);
    __syncwarp();

    // Q a-frags [mt][kt]
    uint32_t qa[2][2][4];
    #pragma unroll
    for (int mt = 0; mt < 2; mt++)
        #pragma unroll
        for (int kt = 0; kt < 2; kt++) {
            uint32_t addr = qsu +
                (uint32_t)(((mt * 16 + (lane & 15)) * ATT_LD) + kt * 16 + (lane >> 4) * 8) * 2;
            LDSM_X4(qa[mt][kt][0], qa[mt][kt][1], qa[mt][kt][2], qa[mt][kt][3], addr);
        }
    // K b-frags [nt][kt] via paired x4
    uint32_t kb[4][2][2];
    #pragma unroll
    for (int p = 0; p < 2; p++)
        #pragma unroll
        for (int kt = 0; kt < 2; kt++) {
            uint32_t addr = ksu +
                (uint32_t)(((p * 16 + ((lane >> 4) & 1) * 8 + (lane & 7)) * ATT_LD)
                           + kt * 16 + ((lane >> 3) & 1) * 8) * 2;
            uint32_t r0, r1, r2, r3;
            LDSM_X4(r0, r1, r2, r3, addr);
            kb[2 * p][kt][0] = r0;     kb[2 * p][kt][1] = r1;
            kb[2 * p + 1][kt][0] = r2; kb[2 * p + 1][kt][1] = r3;
        }

    float S[2][4][4];
    #pragma unroll
    for (int mt = 0; mt < 2; mt++)
        #pragma unroll
        for (int nt = 0; nt < 4; nt++) {
            #pragma unroll
            for (int e = 0; e < 4; e++) S[mt][nt][e] = 0.f;
            mma_16816(S[mt][nt], qa[mt][0], kb[nt][0]);
            mma_16816(S[mt][nt], qa[mt][1], kb[nt][1]);
        }

    // stage V into q buffer (q now in registers)
    __syncwarp();
    #pragma unroll 4
    for (int m = 0; m < 32; m++) qs[m * ATT_LD + lane] = base[m * 960 + 640 + head * 32 + lane];
    __syncwarp();

    // per-lane row/col token ids
    const int g4 = lane >> 2, t2 = (lane & 3) * 2;
    int rtok[4], ctok[8];
    #pragma unroll
    for (int mt = 0; mt < 2; mt++)
        #pragma unroll
        for (int h = 0; h < 2; h++) rtok[mt * 2 + h] = mt * 16 + h * 8 + g4;
    #pragma unroll
    for (int nt = 0; nt < 4; nt++)
        #pragma unroll
        for (int e = 0; e < 2; e++) ctok[nt * 2 + e] = nt * 8 + t2 + e;

    int rreg[4], creg[8];
    if (SHIFT) {
        int wi = win & 511;
        int bd = (wi >> 6) << 2, bh = ((wi >> 3) & 7) << 2, bw = (wi & 7) << 1;
        #pragma unroll
        for (int i = 0; i < 4; i++) {
            int n = rtok[i];
            int d = bd + (n >> 3), h = bh + ((n >> 1) & 3), w = bw + (n & 1);
            rreg[i] = (d < 28 ? 0 : (d < 30 ? 1 : 2)) * 9
                    + (h < 28 ? 0 : (h < 30 ? 1 : 2)) * 3
                    + (w < 14 ? 0 : (w < 15 ? 1 : 2));
        }
        #pragma unroll
        for (int i = 0; i < 8; i++) {
            int n = ctok[i];
            int d = bd + (n >> 3), h = bh + ((n >> 1) & 3), w = bw + (n & 1);
            creg[i] = (d < 28 ? 0 : (d < 30 ? 1 : 2)) * 9
                    + (h < 28 ? 0 : (h < 30 ? 1 : 2)) * 3
                    + (w < 14 ? 0 : (w < 15 ? 1 : 2));
        }
    }

    // bias + mask
    #pragma unroll
    for (int mt = 0; mt < 2; mt++)
        #pragma unroll
        for (int nt = 0; nt < 4; nt++)
            #pragma unroll
            for (int h = 0; h < 2; h++)
                #pragma unroll
                for (int e = 0; e < 2; e++) {
                    int ri = mt * 2 + h, ci = nt * 2 + e;
                    int r = rtok[ri], c = ctok[ci];
                    int idx = ((r >> 3) - (c >> 3) + 3) * 21
                            + (((r >> 1) & 3) - ((c >> 1) & 3) + 3) * 3
                            + ((r & 1) - (c & 1) + 1);
                    float s = S[mt][nt][h * 2 + e] + bias_sh[idx * 10 + head];
                    if (SHIFT && rreg[ri] != creg[ci]) s -= 100.f;
                    S[mt][nt][h * 2 + e] = s;
                }

    // softmax over each of the 4 rows this lane participates in
    float mx[4] = {-1e30f, -1e30f, -1e30f, -1e30f};
    #pragma unroll
    for (int mt = 0; mt < 2; mt++)
        #pragma unroll
        for (int nt = 0; nt < 4; nt++)
            #pragma unroll
            for (int h = 0; h < 2; h++) {
                mx[mt*2+h] = fmaxf(mx[mt*2+h], fmaxf(S[mt][nt][h*2], S[mt][nt][h*2+1]));
            }
    #pragma unroll
    for (int i = 0; i < 4; i++) {
        mx[i] = fmaxf(mx[i], __shfl_xor_sync(0xffffffffu, mx[i], 1));
        mx[i] = fmaxf(mx[i], __shfl_xor_sync(0xffffffffu, mx[i], 2));
    }
    float sm[4] = {0.f, 0.f, 0.f, 0.f};
    #pragma unroll
    for (int mt = 0; mt < 2; mt++)
        #pragma unroll
        for (int nt = 0; nt < 4; nt++)
            #pragma unroll
            for (int h = 0; h < 2; h++)
                #pragma unroll
                for (int e = 0; e < 2; e++) {
                    float ev = __expf(S[mt][nt][h*2+e] - mx[mt*2+h]);
                    S[mt][nt][h*2+e] = ev;
                    sm[mt*2+h] += ev;
                }
    #pragma unroll
    for (int i = 0; i < 4; i++) {
        sm[i] += __shfl_xor_sync(0xffffffffu, sm[i], 1);
        sm[i] += __shfl_xor_sync(0xffffffffu, sm[i], 2);
    }
    float inv[4];
    #pragma unroll
    for (int i = 0; i < 4; i++) inv[i] = 1.f / sm[i];

    // pack P a-frags [mt][kt] (kt tile <- S n-tiles 2kt, 2kt+1)
    uint32_t pa[2][2][4];
    #pragma unroll
    for (int mt = 0; mt < 2; mt++)
        #pragma unroll
        for (int kt = 0; kt < 2; kt++) {
            pa[mt][kt][0] = packbf2(S[mt][2*kt][0],   S[mt][2*kt][1]);
            pa[mt][kt][1] = packbf2(S[mt][2*kt][2],   S[mt][2*kt][3]);
            pa[mt][kt][2] = packbf2(S[mt][2*kt+1][0], S[mt][2*kt+1][1]);
            pa[mt][kt][3] = packbf2(S[mt][2*kt+1][2], S[mt][2*kt+1][3]);
        }

    // V b-frags [nt][kt] via paired x4 trans (nt = dim tiles, kt = token tiles)
    uint32_t vb[4][2][2];
    #pragma unroll
    for (int p = 0; p < 2; p++)
        #pragma unroll
        for (int kt = 0; kt < 2; kt++) {
            uint32_t addr = qsu +
                (uint32_t)(((kt * 16 + ((lane >> 3) & 1) * 8 + (lane & 7)) * ATT_LD)
                           + (2 * p + ((lane >> 4) & 1)) * 8) * 2;
            uint32_t r0, r1, r2, r3;
            LDSM_X4_TRANS(r0, r1, r2, r3, addr);
            vb[2 * p][kt][0] = r0;     vb[2 * p][kt][1] = r1;
            vb[2 * p + 1][kt][0] = r2; vb[2 * p + 1][kt][1] = r3;
        }

    // O = P @ V^T
    float O[2][4][4];
    #pragma unroll
    for (int mt = 0; mt < 2; mt++)
        #pragma unroll
        for (int nt = 0; nt < 4; nt++) {
            #pragma unroll
            for (int e = 0; e < 4; e++) O[mt][nt][e] = 0.f;
            mma_16816(O[mt][nt], pa[mt][0], vb[nt][0]);
            mma_16816(O[mt][nt], pa[mt][1], vb[nt][1]);
        }

    // scale by 1/sum and store
    bf16* obase = out + (size_t)win * 32 * 320 + head * 32;
    #pragma unroll
    for (int mt = 0; mt < 2; mt++)
        #pragma unroll
        for (int nt = 0; nt < 4; nt++)
            #pragma unroll
            for (int h = 0; h < 2; h++) {
                int r = mt * 16 + h * 8 + g4;
                float iv = inv[mt * 2 + h];
                *(__nv_bfloat162*)(obase + (size_t)r * 320 + nt * 8 + t2) =
                    __floats2bfloat162_rn(O[mt][nt][h*2] * iv, O[mt][nt][h*2+1] * iv);
            }
}

// ---------------------------------------------------------------------------
// Host orchestration
// ---------------------------------------------------------------------------
static void run_block(bool shift, const float* const* p, bf16* wb,
                      float* t, bf16* xw, bf16* qkv, bf16* attn, bf16* mlp) {
    const float* ln1g = p[0];  const float* ln1b = p[1];
    const float* qkvb = p[3];  const float* bias = p[4];
    const float* projb = p[6];
    const float* ln2g = p[7];  const float* ln2b = p[8];
    const float* f1b = p[10];  const float* f2b = p[12];

    if (shift) k_ln<true, true ><<<16384, 256>>>(t, ln1g, ln1b, xw);
    else       k_ln<true, false><<<16384, 256>>>(t, ln1g, ln1b, xw);

    k_gemm_mma<0, false><<<dim3(15, 1024), 128>>>(xw, wb + WOFF_QKV, qkvb, qkv, 320, 960);

    if (shift) k_attn<true ><<<10240, 128>>>(qkv, bias, attn);
    else       k_attn<false><<<10240, 128>>>(qkv, bias, attn);

    if (shift) k_gemm_mma<2, true ><<<dim3(5, 1024), 128>>>(attn, wb + WOFF_PROJ, projb, t, 320, 320);
    else       k_gemm_mma<2, false><<<dim3(5, 1024), 128>>>(attn, wb + WOFF_PROJ, projb, t, 320, 320);

    k_ln<false, false><<<16384, 256>>>(t, ln2g, ln2b, xw);

    k_gemm_mma<1, false><<<dim3(20, 1024), 128>>>(xw, wb + WOFF_F1, f1b, mlp, 320, 1280);

    k_gemm_mma<3, false><<<dim3(5, 1024), 128>>>(mlp, wb + WOFF_F2, f2b, t, 1280, 320);
}

extern "C" void kernel_launch(void* const* d_in, const int* in_sizes, int n_in,
                              void* d_out, int out_size) {
    (void)in_sizes; (void)n_in; (void)out_size;
    const float* x = (const float*)d_in[0];

    void *pt, *pxw, *pqkv, *pattn, *pmlp, *pwb;
    cudaGetSymbolAddress(&pt,    g_t);
    cudaGetSymbolAddress(&pxw,   g_xw);
    cudaGetSymbolAddress(&pqkv,  g_qkv);
    cudaGetSymbolAddress(&pattn, g_attn);
    cudaGetSymbolAddress(&pmlp,  g_mlp);
    cudaGetSymbolAddress(&pwb,   g_wb);
    float* t   = (float*)pt;
    bf16* xw   = (bf16*)pxw;
    bf16* qkv  = (bf16*)pqkv;
    bf16* attn = (bf16*)pattn;
    bf16* mlp  = (bf16*)pmlp;
    bf16* wb0  = (bf16*)pwb;
    bf16* wb1  = wb0 + 1228800;

    const float* b1[13], * b2[13];
    for (int i = 0; i < 13; i++) b1[i] = (const float*)d_in[1 + i];
    for (int i = 0; i < 13; i++) b2[i] = (const float*)d_in[14 + i];

    k_wconv<<<dim3(10, 30), dim3(32, 8)>>>(b1[2],  wb0 + WOFF_QKV, 320, 960);
    k_wconv<<<dim3(10, 10), dim3(32, 8)>>>(b1[5],  wb0 + WOFF_PROJ, 320, 320);
    k_wconv<<<dim3(10, 40), dim3(32, 8)>>>(b1[9],  wb0 + WOFF_F1,  320, 1280);
    k_wconv<<<dim3(40, 10), dim3(32, 8)>>>(b1[11], wb0 + WOFF_F2, 1280, 320);
    k_wconv<<<dim3(10, 30), dim3(32, 8)>>>(b2[2],  wb1 + WOFF_QKV, 320, 960);
    k_wconv<<<dim3(10, 10), dim3(32, 8)>>>(b2[5],  wb1 + WOFF_PROJ, 320, 320);
    k_wconv<<<dim3(10, 40), dim3(32, 8)>>>(b2[9],  wb1 + WOFF_F1,  320, 1280);
    k_wconv<<<dim3(40, 10), dim3(32, 8)>>>(b2[11], wb1 + WOFF_F2, 1280, 320);

    // (B,C,L) -> (B,L,C)
    k_tin<<<dim3(L_ / 32, C_ / 32, B_), dim3(32, 8)>>>(x, t);

    run_block(false, b1, wb0, t, xw, qkv, attn, mlp);
    run_block(true,  b2, wb1, t, xw, qkv, attn, mlp);

    // (B,L,C) -> (B,C,L)
    k_tout<<<dim3(L_ / 32, C_ / 32, B_), dim3(32, 8)>>>(t, (float*)d_out);
}

// round 12
// speedup vs baseline: 4.2535x; 1.0110x over previous
#include <cuda_runtime.h>
#include <cuda_bf16.h>
#include <math.h>
#include <stdint.h>

// ---------------------------------------------------------------------------
// Problem constants
// ---------------------------------------------------------------------------
#define B_      8
#define C_      320
#define D_      32
#define H_      32
#define W_      16
#define L_      16384          // D*H*W
#define M_      131072         // B*L   (tokens)
#define QK_SCALE 0.17677669529663687f  // 1/sqrt(32)

typedef __nv_bfloat16 bf16;

// ---------------------------------------------------------------------------
// Portable tensor-core PTX helpers (sm_80+ ISA)
// ---------------------------------------------------------------------------
__device__ __forceinline__ uint32_t smem_to_u32(const void* p) {
    uint32_t a;
    asm("{ .reg .u64 t; cvta.to.shared.u64 t, %1; cvt.u32.u64 %0, t; }" : "=r"(a) : "l"(p));
    return a;
}
__device__ __forceinline__ void cp_async16(uint32_t dst, const void* src) {
    asm volatile("cp.async.cg.shared.global [%0], [%1], 16;" :: "r"(dst), "l"(src));
}
#define CP_COMMIT() asm volatile("cp.async.commit_group;" ::: "memory")
#define CP_WAIT1()  asm volatile("cp.async.wait_group 1;" ::: "memory")
#define CP_WAIT0()  asm volatile("cp.async.wait_group 0;" ::: "memory")

#define LDSM_X4(r0, r1, r2, r3, a) \
    asm volatile("ldmatrix.sync.aligned.m8n8.x4.shared.b16 {%0,%1,%2,%3}, [%4];" \
                 : "=r"(r0), "=r"(r1), "=r"(r2), "=r"(r3) : "r"(a))
#define LDSM_X4_TRANS(r0, r1, r2, r3, a) \
    asm volatile("ldmatrix.sync.aligned.m8n8.x4.trans.shared.b16 {%0,%1,%2,%3}, [%4];" \
                 : "=r"(r0), "=r"(r1), "=r"(r2), "=r"(r3) : "r"(a))

__device__ __forceinline__ void mma_16816(float* c, const uint32_t* a, const uint32_t* b) {
    asm volatile(
        "mma.sync.aligned.m16n8k16.row.col.f32.bf16.bf16.f32 "
        "{%0,%1,%2,%3}, {%4,%5,%6,%7}, {%8,%9}, {%0,%1,%2,%3};"
        : "+f"(c[0]), "+f"(c[1]), "+f"(c[2]), "+f"(c[3])
        : "r"(a[0]), "r"(a[1]), "r"(a[2]), "r"(a[3]), "r"(b[0]), "r"(b[1]));
}
__device__ __forceinline__ uint32_t packbf2(float lo, float hi) {
    __nv_bfloat162 v = __floats2bfloat162_rn(lo, hi);
    return *(uint32_t*)&v;
}

// ---------------------------------------------------------------------------
// Scratch (static device globals)
// ---------------------------------------------------------------------------
__device__ float g_t   [(size_t)M_ * C_];      // residual stream fp32 (B,L,C)
__device__ bf16  g_xw  [(size_t)M_ * C_];      // LN output bf16
__device__ bf16  g_qkv [(size_t)M_ * 960];     // qkv bf16, windowed rows
__device__ bf16  g_attn[(size_t)M_ * C_];      // attention out bf16, windowed rows
__device__ bf16  g_mlp [(size_t)M_ * 1280];    // gelu(f1) out bf16
__device__ bf16  g_wb[2][1228800];             // [N,K] bf16 weights per block
#define WOFF_QKV 0
#define WOFF_PROJ 307200
#define WOFF_F1 409600
#define WOFF_F2 819200

// ---------------------------------------------------------------------------
// Window geometry
// ---------------------------------------------------------------------------
__device__ __forceinline__ int win_src_row(int r, bool shift) {
    int b   = r >> 14;
    int rem = r & 16383;
    int wi  = rem >> 5;
    int n   = rem & 31;
    int d = ((wi >> 6) << 2)        + (n >> 3);
    int h = (((wi >> 3) & 7) << 2)  + ((n >> 1) & 3);
    int w = ((wi & 7) << 1)         + (n & 1);
    if (shift) { d = (d + 2) & 31; h = (h + 2) & 31; w = (w + 1) & 15; }
    return (b << 14) + (d << 9) + (h << 4) + w;
}

// ---------------------------------------------------------------------------
// Transposes (fp32)
// ---------------------------------------------------------------------------
__global__ void k_tin(const float* __restrict__ x, float* __restrict__ t) {
    __shared__ float tile[32][33];
    int b = blockIdx.z, l0 = blockIdx.x * 32, c0 = blockIdx.y * 32;
    int tx = threadIdx.x, ty = threadIdx.y;
    #pragma unroll
    for (int i = ty; i < 32; i += 8)
        tile[i][tx] = x[((size_t)(b * C_ + c0 + i)) * L_ + l0 + tx];
    __syncthreads();
    #pragma unroll
    for (int i = ty; i < 32; i += 8)
        t[((size_t)(b * L_ + l0 + i)) * C_ + c0 + tx] = tile[tx][i];
}
__global__ void k_tout(const float* __restrict__ t, float* __restrict__ o) {
    __shared__ float tile[32][33];
    int b = blockIdx.z, l0 = blockIdx.x * 32, c0 = blockIdx.y * 32;
    int tx = threadIdx.x, ty = threadIdx.y;
    #pragma unroll
    for (int i = ty; i < 32; i += 8)
        tile[i][tx] = t[((size_t)(b * L_ + l0 + i)) * C_ + c0 + tx];
    __syncthreads();
    #pragma unroll
    for (int i = ty; i < 32; i += 8)
        o[((size_t)(b * C_ + c0 + i)) * L_ + l0 + tx] = tile[tx][i];
}

// ---------------------------------------------------------------------------
// Weight convert + transpose: W[K,N] fp32 -> out[N,K] bf16
// ---------------------------------------------------------------------------
__global__ void k_wconv(const float* __restrict__ Wm, bf16* __restrict__ out, int K, int N) {
    __shared__ float tile[32][33];
    int k0 = blockIdx.x * 32, n0 = blockIdx.y * 32;
    int tx = threadIdx.x, ty = threadIdx.y;
    #pragma unroll
    for (int i = ty; i < 32; i += 8)
        tile[i][tx] = Wm[(size_t)(k0 + i) * N + n0 + tx];
    __syncthreads();
    #pragma unroll
    for (int i = ty; i < 32; i += 8)
        out[(size_t)(n0 + i) * K + k0 + tx] = __float2bfloat16(tile[tx][i]);
}

// ---------------------------------------------------------------------------
// LayerNorm (one warp per token) -> bf16, optional windowed gather
// ---------------------------------------------------------------------------
template<bool WIN, bool SHIFT>
__global__ void k_ln(const float* __restrict__ t, const float* __restrict__ gam,
                     const float* __restrict__ bet, bf16* __restrict__ out) {
    int warp = (blockIdx.x * blockDim.x + threadIdx.x) >> 5;
    int lane = threadIdx.x & 31;
    if (warp >= M_) return;
    int src = WIN ? win_src_row(warp, SHIFT) : warp;
    const float* row = t + (size_t)src * C_;
    float v[10]; float s = 0.f;
    #pragma unroll
    for (int i = 0; i < 10; i++) { v[i] = row[lane + 32 * i]; s += v[i]; }
    #pragma unroll
    for (int o = 16; o; o >>= 1) s += __shfl_xor_sync(0xffffffffu, s, o);
    float mu = s * (1.f / C_); float var = 0.f;
    #pragma unroll
    for (int i = 0; i < 10; i++) { float d = v[i] - mu; var += d * d; }
    #pragma unroll
    for (int o = 16; o; o >>= 1) var += __shfl_xor_sync(0xffffffffu, var, o);
    float inv = rsqrtf(var * (1.f / C_) + 1e-5f);
    bf16* orow = out + (size_t)warp * C_;
    #pragma unroll
    for (int i = 0; i < 10; i++) {
        int c = lane + 32 * i;
        orow[c] = __float2bfloat16((v[i] - mu) * inv * gam[c] + bet[c]);
    }
}

// ---------------------------------------------------------------------------
// HMMA GEMM: BM=128, BN=64, BK=32, 128 threads (2x2 warps of 64x32),
// 3-stage cp.async, static smem 46080B.  B-frags via paired ldmatrix.x4.
// Single barrier per chunk: issue target (kc+2)%3 == (kc-1)%3, whose readers
// (iter kc-1 mma) all passed this iteration's barrier.  Plain
// __launch_bounds__(128) — minBlocks=4 reverted (R10 container failure).
// EPI: 0 bf16 (+bias) | 1 bf16 gelu | 2 fp32 += win-reversed | 3 fp32 += plain
// ---------------------------------------------------------------------------
#define LDA 40
#define G_STAGES 3
#define G_ASZ (128 * LDA)
#define G_BSZ (64 * LDA)

template<int EPI, bool SHIFT>
__global__ __launch_bounds__(128)
void k_gemm_mma(const bf16* __restrict__ A, const bf16* __restrict__ Wt,
                const float* __restrict__ bias, void* __restrict__ OutP,
                int K, int Nn) {
    __shared__ __align__(16) bf16 Asm[G_STAGES][G_ASZ];
    __shared__ __align__(16) bf16 Bsm[G_STAGES][G_BSZ];

    const int tid = threadIdx.x, lane = tid & 31, wid = tid >> 5;
    const int wm = wid & 1, wn = wid >> 1;
    const int m0 = blockIdx.y * 128, n0 = blockIdx.x * 64;

    uint32_t sA[G_STAGES], sB[G_STAGES];
    #pragma unroll
    for (int s = 0; s < G_STAGES; s++) {
        sA[s] = smem_to_u32(Asm[s]);
        sB[s] = smem_to_u32(Bsm[s]);
    }

    float acc[4][4][4];
    #pragma unroll
    for (int i = 0; i < 4; i++)
        #pragma unroll
        for (int j = 0; j < 4; j++)
            #pragma unroll
            for (int k = 0; k < 4; k++) acc[i][j][k] = 0.f;

    const int NC = K >> 5;

    auto issue = [&](int kc, int buf) {
        const bf16* Ag = A + (size_t)m0 * K + kc * 32;
        #pragma unroll
        for (int i = 0; i < 4; i++) {
            int v = tid + i * 128;
            int row = v >> 2, c8 = (v & 3) * 8;
            cp_async16(sA[buf] + (uint32_t)(row * LDA + c8) * 2,
                       Ag + (size_t)row * K + c8);
        }
        const bf16* Bg = Wt + (size_t)n0 * K + kc * 32;
        #pragma unroll
        for (int i = 0; i < 2; i++) {
            int v = tid + i * 128;
            int row = v >> 2, c8 = (v & 3) * 8;
            cp_async16(sB[buf] + (uint32_t)(row * LDA + c8) * 2,
                       Bg + (size_t)row * K + c8);
        }
    };

    issue(0, 0); CP_COMMIT();
    issue(1, 1); CP_COMMIT();

    for (int kc = 0; kc < NC; kc++) {
        int buf = kc % G_STAGES;
        if (kc + 2 < NC) CP_WAIT1(); else CP_WAIT0();
        __syncthreads();
        // prefetch next-next chunk NOW: its buffer's readers (iter kc-1) have
        // all passed the barrier above; overlaps loads with this chunk's mma.
        if (kc + 2 < NC) { issue(kc + 2, (kc + 2) % G_STAGES); CP_COMMIT(); }

        #pragma unroll
        for (int ks = 0; ks < 2; ks++) {
            int k0 = ks * 16;
            uint32_t afr[4][4];
            #pragma unroll
            for (int mt = 0; mt < 4; mt++) {
                uint32_t addr = sA[buf] +
                    (uint32_t)(((wm * 64 + mt * 16 + (lane & 15)) * LDA)
                               + k0 + ((lane >> 4) * 8)) * 2;
                LDSM_X4(afr[mt][0], afr[mt][1], afr[mt][2], afr[mt][3], addr);
            }
            // B frags: 2 x ldmatrix.x4, each covering an n-tile pair
            uint32_t bfr[4][2];
            #pragma unroll
            for (int p = 0; p < 2; p++) {
                uint32_t addr = sB[buf] +
                    (uint32_t)(((wn * 32 + p * 16 + ((lane >> 4) & 1) * 8 + (lane & 7)) * LDA)
                               + k0 + ((lane >> 3) & 1) * 8) * 2;
                uint32_t r0, r1, r2, r3;
                LDSM_X4(r0, r1, r2, r3, addr);
                bfr[2 * p][0] = r0;     bfr[2 * p][1] = r1;
                bfr[2 * p + 1][0] = r2; bfr[2 * p + 1][1] = r3;
            }
            #pragma unroll
            for (int mt = 0; mt < 4; mt++)
                #pragma unroll
                for (int nt = 0; nt < 4; nt++)
                    mma_16816(acc[mt][nt], afr[mt], bfr[nt]);
        }
    }

    const int qr = lane >> 2, qc = (lane & 3) * 2;
    #pragma unroll
    for (int nt = 0; nt < 4; nt++) {
        int gn = n0 + wn * 32 + nt * 8 + qc;
        float b0 = bias[gn], b1 = bias[gn + 1];
        #pragma unroll
        for (int mt = 0; mt < 4; mt++) {
            int gmA = m0 + wm * 64 + mt * 16 + qr;
            float v0 = acc[mt][nt][0] + b0;
            float v1 = acc[mt][nt][1] + b1;
            float v2 = acc[mt][nt][2] + b0;
            float v3 = acc[mt][nt][3] + b1;
            if (EPI == 1) {
                v0 = 0.5f * v0 * (1.f + erff(v0 * 0.70710678118654752f));
                v1 = 0.5f * v1 * (1.f + erff(v1 * 0.70710678118654752f));
                v2 = 0.5f * v2 * (1.f + erff(v2 * 0.70710678118654752f));
                v3 = 0.5f * v3 * (1.f + erff(v3 * 0.70710678118654752f));
            }
            if (EPI == 0 || EPI == 1) {
                bf16* Ob = (bf16*)OutP;
                *(__nv_bfloat162*)(Ob + (size_t)gmA * Nn + gn) = __floats2bfloat162_rn(v0, v1);
                *(__nv_bfloat162*)(Ob + (size_t)(gmA + 8) * Nn + gn) = __floats2bfloat162_rn(v2, v3);
            } else {
                float* Of = (float*)OutP;
                int r0 = (EPI == 2) ? win_src_row(gmA, SHIFT) : gmA;
                int r1 = (EPI == 2) ? win_src_row(gmA + 8, SHIFT) : (gmA + 8);
                float* p0 = Of + (size_t)r0 * 320 + gn;
                float* p1 = Of + (size_t)r1 * 320 + gn;
                p0[0] += v0; p0[1] += v1;
                p1[0] += v2; p1[1] += v3;
            }
        }
    }
}

// ---------------------------------------------------------------------------
// Warp-mma windowed attention: one warp per (window, head); 4 warps/block.
// S = Q@K^T via m16n8k16; softmax in c-frags; P repacked to a-frags; O = P@V
// with V b-frags via ldmatrix.x4.trans.
// ---------------------------------------------------------------------------
#define ATT_LD 40

template<bool SHIFT>
__global__ __launch_bounds__(128)
void k_attn(const bf16* __restrict__ qkv,
            const float* __restrict__ biasTab,
            bf16* __restrict__ out) {
    __shared__ float bias_sh[1470];
    __shared__ __align__(16) bf16 kbuf[4][32 * ATT_LD];
    __shared__ __align__(16) bf16 qvbuf[4][32 * ATT_LD];   // q, then v

    int tid = threadIdx.x, lane = tid & 31, wrp = tid >> 5;
    for (int i = tid; i < 1470; i += 128) bias_sh[i] = biasTab[i];
    __syncthreads();

    int gwh = blockIdx.x * 4 + wrp;
    int win = gwh / 10;
    int head = gwh - win * 10;
    const bf16* base = qkv + (size_t)win * 32 * 960;
    bf16* ks = kbuf[wrp];
    bf16* qs = qvbuf[wrp];
    uint32_t ksu = smem_to_u32(ks), qsu = smem_to_u32(qs);

    // stage K (rows=tokens) and Q (scaled)
    #pragma unroll 4
    for (int m = 0; m < 32; m++) ks[m * ATT_LD + lane] = base[m * 960 + 320 + head * 32 + lane];
    #pragma unroll 4
    for (int m = 0; m < 32; m++)
        qs[m * ATT_LD + lane] =
            __float2bfloat16(__bfloat162float(base[m * 960 + head * 32 + lane]) * QK_SCALE);
    __syncwarp();

    // Q a-frags [mt][kt]
    uint32_t qa[2][2][4];
    #pragma unroll
    for (int mt = 0; mt < 2; mt++)
        #pragma unroll
        for (int kt = 0; kt < 2; kt++) {
            uint32_t addr = qsu +
                (uint32_t)(((mt * 16 + (lane & 15)) * ATT_LD) + kt * 16 + (lane >> 4) * 8) * 2;
            LDSM_X4(qa[mt][kt][0], qa[mt][kt][1], qa[mt][kt][2], qa[mt][kt][3], addr);
        }
    // K b-frags [nt][kt] via paired x4
    uint32_t kb[4][2][2];
    #pragma unroll
    for (int p = 0; p < 2; p++)
        #pragma unroll
        for (int kt = 0; kt < 2; kt++) {
            uint32_t addr = ksu +
                (uint32_t)(((p * 16 + ((lane >> 4) & 1) * 8 + (lane & 7)) * ATT_LD)
                           + kt * 16 + ((lane >> 3) & 1) * 8) * 2;
            uint32_t r0, r1, r2, r3;
            LDSM_X4(r0, r1, r2, r3, addr);
            kb[2 * p][kt][0] = r0;     kb[2 * p][kt][1] = r1;
            kb[2 * p + 1][kt][0] = r2; kb[2 * p + 1][kt][1] = r3;
        }

    float S[2][4][4];
    #pragma unroll
    for (int mt = 0; mt < 2; mt++)
        #pragma unroll
        for (int nt = 0; nt < 4; nt++) {
            #pragma unroll
            for (int e = 0; e < 4; e++) S[mt][nt][e] = 0.f;
            mma_16816(S[mt][nt], qa[mt][0], kb[nt][0]);
            mma_16816(S[mt][nt], qa[mt][1], kb[nt][1]);
        }

    // stage V into q buffer (q now in registers)
    __syncwarp();
    #pragma unroll 4
    for (int m = 0; m < 32; m++) qs[m * ATT_LD + lane] = base[m * 960 + 640 + head * 32 + lane];
    __syncwarp();

    // per-lane row/col token ids
    const int g4 = lane >> 2, t2 = (lane & 3) * 2;
    int rtok[4], ctok[8];
    #pragma unroll
    for (int mt = 0; mt < 2; mt++)
        #pragma unroll
        for (int h = 0; h < 2; h++) rtok[mt * 2 + h] = mt * 16 + h * 8 + g4;
    #pragma unroll
    for (int nt = 0; nt < 4; nt++)
        #pragma unroll
        for (int e = 0; e < 2; e++) ctok[nt * 2 + e] = nt * 8 + t2 + e;

    int rreg[4], creg[8];
    if (SHIFT) {
        int wi = win & 511;
        int bd = (wi >> 6) << 2, bh = ((wi >> 3) & 7) << 2, bw = (wi & 7) << 1;
        #pragma unroll
        for (int i = 0; i < 4; i++) {
            int n = rtok[i];
            int d = bd + (n >> 3), h = bh + ((n >> 1) & 3), w = bw + (n & 1);
            rreg[i] = (d < 28 ? 0 : (d < 30 ? 1 : 2)) * 9
                    + (h < 28 ? 0 : (h < 30 ? 1 : 2)) * 3
                    + (w < 14 ? 0 : (w < 15 ? 1 : 2));
        }
        #pragma unroll
        for (int i = 0; i < 8; i++) {
            int n = ctok[i];
            int d = bd + (n >> 3), h = bh + ((n >> 1) & 3), w = bw + (n & 1);
            creg[i] = (d < 28 ? 0 : (d < 30 ? 1 : 2)) * 9
                    + (h < 28 ? 0 : (h < 30 ? 1 : 2)) * 3
                    + (w < 14 ? 0 : (w < 15 ? 1 : 2));
        }
    }

    // bias + mask
    #pragma unroll
    for (int mt = 0; mt < 2; mt++)
        #pragma unroll
        for (int nt = 0; nt < 4; nt++)
            #pragma unroll
            for (int h = 0; h < 2; h++)
                #pragma unroll
                for (int e = 0; e < 2; e++) {
                    int ri = mt * 2 + h, ci = nt * 2 + e;
                    int r = rtok[ri], c = ctok[ci];
                    int idx = ((r >> 3) - (c >> 3) + 3) * 21
                            + (((r >> 1) & 3) - ((c >> 1) & 3) + 3) * 3
                            + ((r & 1) - (c & 1) + 1);
                    float s = S[mt][nt][h * 2 + e] + bias_sh[idx * 10 + head];
                    if (SHIFT && rreg[ri] != creg[ci]) s -= 100.f;
                    S[mt][nt][h * 2 + e] = s;
                }

    // softmax over each of the 4 rows this lane participates in
    float mx[4] = {-1e30f, -1e30f, -1e30f, -1e30f};
    #pragma unroll
    for (int mt = 0; mt < 2; mt++)
        #pragma unroll
        for (int nt = 0; nt < 4; nt++)
            #pragma unroll
            for (int h = 0; h < 2; h++) {
                mx[mt*2+h] = fmaxf(mx[mt*2+h], fmaxf(S[mt][nt][h*2], S[mt][nt][h*2+1]));
            }
    #pragma unroll
    for (int i = 0; i < 4; i++) {
        mx[i] = fmaxf(mx[i], __shfl_xor_sync(0xffffffffu, mx[i], 1));
        mx[i] = fmaxf(mx[i], __shfl_xor_sync(0xffffffffu, mx[i], 2));
    }
    float sm[4] = {0.f, 0.f, 0.f, 0.f};
    #pragma unroll
    for (int mt = 0; mt < 2; mt++)
        #pragma unroll
        for (int nt = 0; nt < 4; nt++)
            #pragma unroll
            for (int h = 0; h < 2; h++)
                #pragma unroll
                for (int e = 0; e < 2; e++) {
                    float ev = __expf(S[mt][nt][h*2+e] - mx[mt*2+h]);
                    S[mt][nt][h*2+e] = ev;
                    sm[mt*2+h] += ev;
                }
    #pragma unroll
    for (int i = 0; i < 4; i++) {
        sm[i] += __shfl_xor_sync(0xffffffffu, sm[i], 1);
        sm[i] += __shfl_xor_sync(0xffffffffu, sm[i], 2);
    }
    float inv[4];
    #pragma unroll
    for (int i = 0; i < 4; i++) inv[i] = 1.f / sm[i];

    // pack P a-frags [mt][kt] (kt tile <- S n-tiles 2kt, 2kt+1)
    uint32_t pa[2][2][4];
    #pragma unroll
    for (int mt = 0; mt < 2; mt++)
        #pragma unroll
        for (int kt = 0; kt < 2; kt++) {
            pa[mt][kt][0] = packbf2(S[mt][2*kt][0],   S[mt][2*kt][1]);
            pa[mt][kt][1] = packbf2(S[mt][2*kt][2],   S[mt][2*kt][3]);
            pa[mt][kt][2] = packbf2(S[mt][2*kt+1][0], S[mt][2*kt+1][1]);
            pa[mt][kt][3] = packbf2(S[mt][2*kt+1][2], S[mt][2*kt+1][3]);
        }

    // V b-frags [nt][kt] via paired x4 trans (nt = dim tiles, kt = token tiles)
    uint32_t vb[4][2][2];
    #pragma unroll
    for (int p = 0; p < 2; p++)
        #pragma unroll
        for (int kt = 0; kt < 2; kt++) {
            uint32_t addr = qsu +
                (uint32_t)(((kt * 16 + ((lane >> 3) & 1) * 8 + (lane & 7)) * ATT_LD)
                           + (2 * p + ((lane >> 4) & 1)) * 8) * 2;
            uint32_t r0, r1, r2, r3;
            LDSM_X4_TRANS(r0, r1, r2, r3, addr);
            vb[2 * p][kt][0] = r0;     vb[2 * p][kt][1] = r1;
            vb[2 * p + 1][kt][0] = r2; vb[2 * p + 1][kt][1] = r3;
        }

    // O = P @ V^T
    float O[2][4][4];
    #pragma unroll
    for (int mt = 0; mt < 2; mt++)
        #pragma unroll
        for (int nt = 0; nt < 4; nt++) {
            #pragma unroll
            for (int e = 0; e < 4; e++) O[mt][nt][e] = 0.f;
            mma_16816(O[mt][nt], pa[mt][0], vb[nt][0]);
            mma_16816(O[mt][nt], pa[mt][1], vb[nt][1]);
        }

    // scale by 1/sum and store
    bf16* obase = out + (size_t)win * 32 * 320 + head * 32;
    #pragma unroll
    for (int mt = 0; mt < 2; mt++)
        #pragma unroll
        for (int nt = 0; nt < 4; nt++)
            #pragma unroll
            for (int h = 0; h < 2; h++) {
                int r = mt * 16 + h * 8 + g4;
                float iv = inv[mt * 2 + h];
                *(__nv_bfloat162*)(obase + (size_t)r * 320 + nt * 8 + t2) =
                    __floats2bfloat162_rn(O[mt][nt][h*2] * iv, O[mt][nt][h*2+1] * iv);
            }
}

// ---------------------------------------------------------------------------
// Host orchestration
// ---------------------------------------------------------------------------
static void run_block(bool shift, const float* const* p, bf16* wb,
                      float* t, bf16* xw, bf16* qkv, bf16* attn, bf16* mlp) {
    const float* ln1g = p[0];  const float* ln1b = p[1];
    const float* qkvb = p[3];  const float* bias = p[4];
    const float* projb = p[6];
    const float* ln2g = p[7];  const float* ln2b = p[8];
    const float* f1b = p[10];  const float* f2b = p[12];

    if (shift) k_ln<true, true ><<<16384, 256>>>(t, ln1g, ln1b, xw);
    else       k_ln<true, false><<<16384, 256>>>(t, ln1g, ln1b, xw);

    k_gemm_mma<0, false><<<dim3(15, 1024), 128>>>(xw, wb + WOFF_QKV, qkvb, qkv, 320, 960);

    if (shift) k_attn<true ><<<10240, 128>>>(qkv, bias, attn);
    else       k_attn<false><<<10240, 128>>>(qkv, bias, attn);

    if (shift) k_gemm_mma<2, true ><<<dim3(5, 1024), 128>>>(attn, wb + WOFF_PROJ, projb, t, 320, 320);
    else       k_gemm_mma<2, false><<<dim3(5, 1024), 128>>>(attn, wb + WOFF_PROJ, projb, t, 320, 320);

    k_ln<false, false><<<16384, 256>>>(t, ln2g, ln2b, xw);

    k_gemm_mma<1, false><<<dim3(20, 1024), 128>>>(xw, wb + WOFF_F1, f1b, mlp, 320, 1280);

    k_gemm_mma<3, false><<<dim3(5, 1024), 128>>>(mlp, wb + WOFF_F2, f2b, t, 1280, 320);
}

extern "C" void kernel_launch(void* const* d_in, const int* in_sizes, int n_in,
                              void* d_out, int out_size) {
    (void)in_sizes; (void)n_in; (void)out_size;
    const float* x = (const float*)d_in[0];

    void *pt, *pxw, *pqkv, *pattn, *pmlp, *pwb;
    cudaGetSymbolAddress(&pt,    g_t);
    cudaGetSymbolAddress(&pxw,   g_xw);
    cudaGetSymbolAddress(&pqkv,  g_qkv);
    cudaGetSymbolAddress(&pattn, g_attn);
    cudaGetSymbolAddress(&pmlp,  g_mlp);
    cudaGetSymbolAddress(&pwb,   g_wb);
    float* t   = (float*)pt;
    bf16* xw   = (bf16*)pxw;
    bf16* qkv  = (bf16*)pqkv;
    bf16* attn = (bf16*)pattn;
    bf16* mlp  = (bf16*)pmlp;
    bf16* wb0  = (bf16*)pwb;
    bf16* wb1  = wb0 + 1228800;

    const float* b1[13], * b2[13];
    for (int i = 0; i < 13; i++) b1[i] = (const float*)d_in[1 + i];
    for (int i = 0; i < 13; i++) b2[i] = (const float*)d_in[14 + i];

    k_wconv<<<dim3(10, 30), dim3(32, 8)>>>(b1[2],  wb0 + WOFF_QKV, 320, 960);
    k_wconv<<<dim3(10, 10), dim3(32, 8)>>>(b1[5],  wb0 + WOFF_PROJ, 320, 320);
    k_wconv<<<dim3(10, 40), dim3(32, 8)>>>(b1[9],  wb0 + WOFF_F1,  320, 1280);
    k_wconv<<<dim3(40, 10), dim3(32, 8)>>>(b1[11], wb0 + WOFF_F2, 1280, 320);
    k_wconv<<<dim3(10, 30), dim3(32, 8)>>>(b2[2],  wb1 + WOFF_QKV, 320, 960);
    k_wconv<<<dim3(10, 10), dim3(32, 8)>>>(b2[5],  wb1 + WOFF_PROJ, 320, 320);
    k_wconv<<<dim3(10, 40), dim3(32, 8)>>>(b2[9],  wb1 + WOFF_F1,  320, 1280);
    k_wconv<<<dim3(40, 10), dim3(32, 8)>>>(b2[11], wb1 + WOFF_F2, 1280, 320);

    // (B,C,L) -> (B,L,C)
    k_tin<<<dim3(L_ / 32, C_ / 32, B_), dim3(32, 8)>>>(x, t);

    run_block(false, b1, wb0, t, xw, qkv, attn, mlp);
    run_block(true,  b2, wb1, t, xw, qkv, attn, mlp);

    // (B,L,C) -> (B,C,L)
    k_tout<<<dim3(L_ / 32, C_ / 32, B_), dim3(32, 8)>>>(t, (float*)d_out);
}

// round 13
// speedup vs baseline: 4.5788x; 1.0765x over previous
#include <cuda_runtime.h>
#include <cuda_bf16.h>
#include <math.h>
#include <stdint.h>

// ---------------------------------------------------------------------------
// Problem constants
// ---------------------------------------------------------------------------
#define B_      8
#define C_      320
#define D_      32
#define H_      32
#define W_      16
#define L_      16384          // D*H*W
#define M_      131072         // B*L   (tokens)
#define QK_SCALE 0.17677669529663687f  // 1/sqrt(32)

typedef __nv_bfloat16 bf16;

// ---------------------------------------------------------------------------
// Portable tensor-core PTX helpers (sm_80+ ISA)
// ---------------------------------------------------------------------------
__device__ __forceinline__ uint32_t smem_to_u32(const void* p) {
    uint32_t a;
    asm("{ .reg .u64 t; cvta.to.shared.u64 t, %1; cvt.u32.u64 %0, t; }" : "=r"(a) : "l"(p));
    return a;
}
__device__ __forceinline__ void cp_async16(uint32_t dst, const void* src) {
    asm volatile("cp.async.cg.shared.global [%0], [%1], 16;" :: "r"(dst), "l"(src));
}
#define CP_COMMIT() asm volatile("cp.async.commit_group;" ::: "memory")
#define CP_WAIT0()  asm volatile("cp.async.wait_group 0;" ::: "memory")

#define LDSM_X4(r0, r1, r2, r3, a) \
    asm volatile("ldmatrix.sync.aligned.m8n8.x4.shared.b16 {%0,%1,%2,%3}, [%4];" \
                 : "=r"(r0), "=r"(r1), "=r"(r2), "=r"(r3) : "r"(a))
#define LDSM_X4_TRANS(r0, r1, r2, r3, a) \
    asm volatile("ldmatrix.sync.aligned.m8n8.x4.trans.shared.b16 {%0,%1,%2,%3}, [%4];" \
                 : "=r"(r0), "=r"(r1), "=r"(r2), "=r"(r3) : "r"(a))

__device__ __forceinline__ void mma_16816(float* c, const uint32_t* a, const uint32_t* b) {
    asm volatile(
        "mma.sync.aligned.m16n8k16.row.col.f32.bf16.bf16.f32 "
        "{%0,%1,%2,%3}, {%4,%5,%6,%7}, {%8,%9}, {%0,%1,%2,%3};"
        : "+f"(c[0]), "+f"(c[1]), "+f"(c[2]), "+f"(c[3])
        : "r"(a[0]), "r"(a[1]), "r"(a[2]), "r"(a[3]), "r"(b[0]), "r"(b[1]));
}
__device__ __forceinline__ uint32_t packbf2(float lo, float hi) {
    __nv_bfloat162 v = __floats2bfloat162_rn(lo, hi);
    return *(uint32_t*)&v;
}

// ---------------------------------------------------------------------------
// Scratch (static device globals)
// ---------------------------------------------------------------------------
__device__ float g_t   [(size_t)M_ * C_];      // residual stream fp32 (B,L,C)
__device__ bf16  g_xw  [(size_t)M_ * C_];      // LN output bf16
__device__ bf16  g_qkv [(size_t)M_ * 960];     // qkv bf16, windowed rows
__device__ bf16  g_attn[(size_t)M_ * C_];      // attention out bf16, windowed rows
__device__ bf16  g_mlp [(size_t)M_ * 1280];    // gelu(f1) out bf16
__device__ bf16  g_wb[2][1228800];             // [N,K] bf16 weights per block
#define WOFF_QKV 0
#define WOFF_PROJ 307200
#define WOFF_F1 409600
#define WOFF_F2 819200

// ---------------------------------------------------------------------------
// Window geometry
// ---------------------------------------------------------------------------
__device__ __forceinline__ int win_src_row(int r, bool shift) {
    int b   = r >> 14;
    int rem = r & 16383;
    int wi  = rem >> 5;
    int n   = rem & 31;
    int d = ((wi >> 6) << 2)        + (n >> 3);
    int h = (((wi >> 3) & 7) << 2)  + ((n >> 1) & 3);
    int w = ((wi & 7) << 1)         + (n & 1);
    if (shift) { d = (d + 2) & 31; h = (h + 2) & 31; w = (w + 1) & 15; }
    return (b << 14) + (d << 9) + (h << 4) + w;
}

// ---------------------------------------------------------------------------
// Transposes (fp32)
// ---------------------------------------------------------------------------
__global__ void k_tin(const float* __restrict__ x, float* __restrict__ t) {
    __shared__ float tile[32][33];
    int b = blockIdx.z, l0 = blockIdx.x * 32, c0 = blockIdx.y * 32;
    int tx = threadIdx.x, ty = threadIdx.y;
    #pragma unroll
    for (int i = ty; i < 32; i += 8)
        tile[i][tx] = x[((size_t)(b * C_ + c0 + i)) * L_ + l0 + tx];
    __syncthreads();
    #pragma unroll
    for (int i = ty; i < 32; i += 8)
        t[((size_t)(b * L_ + l0 + i)) * C_ + c0 + tx] = tile[tx][i];
}
__global__ void k_tout(const float* __restrict__ t, float* __restrict__ o) {
    __shared__ float tile[32][33];
    int b = blockIdx.z, l0 = blockIdx.x * 32, c0 = blockIdx.y * 32;
    int tx = threadIdx.x, ty = threadIdx.y;
    #pragma unroll
    for (int i = ty; i < 32; i += 8)
        tile[i][tx] = t[((size_t)(b * L_ + l0 + i)) * C_ + c0 + tx];
    __syncthreads();
    #pragma unroll
    for (int i = ty; i < 32; i += 8)
        o[((size_t)(b * C_ + c0 + i)) * L_ + l0 + tx] = tile[tx][i];
}

// ---------------------------------------------------------------------------
// Weight convert + transpose: W[K,N] fp32 -> out[N,K] bf16
// ---------------------------------------------------------------------------
__global__ void k_wconv(const float* __restrict__ Wm, bf16* __restrict__ out, int K, int N) {
    __shared__ float tile[32][33];
    int k0 = blockIdx.x * 32, n0 = blockIdx.y * 32;
    int tx = threadIdx.x, ty = threadIdx.y;
    #pragma unroll
    for (int i = ty; i < 32; i += 8)
        tile[i][tx] = Wm[(size_t)(k0 + i) * N + n0 + tx];
    __syncthreads();
    #pragma unroll
    for (int i = ty; i < 32; i += 8)
        out[(size_t)(n0 + i) * K + k0 + tx] = __float2bfloat16(tile[tx][i]);
}

// ---------------------------------------------------------------------------
// LayerNorm (one warp per token) -> bf16, optional windowed gather
// ---------------------------------------------------------------------------
template<bool WIN, bool SHIFT>
__global__ void k_ln(const float* __restrict__ t, const float* __restrict__ gam,
                     const float* __restrict__ bet, bf16* __restrict__ out) {
    int warp = (blockIdx.x * blockDim.x + threadIdx.x) >> 5;
    int lane = threadIdx.x & 31;
    if (warp >= M_) return;
    int src = WIN ? win_src_row(warp, SHIFT) : warp;
    const float* row = t + (size_t)src * C_;
    float v[10]; float s = 0.f;
    #pragma unroll
    for (int i = 0; i < 10; i++) { v[i] = row[lane + 32 * i]; s += v[i]; }
    #pragma unroll
    for (int o = 16; o; o >>= 1) s += __shfl_xor_sync(0xffffffffu, s, o);
    float mu = s * (1.f / C_); float var = 0.f;
    #pragma unroll
    for (int i = 0; i < 10; i++) { float d = v[i] - mu; var += d * d; }
    #pragma unroll
    for (int o = 16; o; o >>= 1) var += __shfl_xor_sync(0xffffffffu, var, o);
    float inv = rsqrtf(var * (1.f / C_) + 1e-5f);
    bf16* orow = out + (size_t)warp * C_;
    #pragma unroll
    for (int i = 0; i < 10; i++) {
        int c = lane + 32 * i;
        orow[c] = __float2bfloat16((v[i] - mu) * inv * gam[c] + bet[c]);
    }
}

// ---------------------------------------------------------------------------
// HMMA GEMM: BM=128, BN=160, BK=32.  256 threads (8 warps, 4m x 2n),
// warp tile 32x80.  2-stage cp.async, ONE barrier per chunk (the top barrier
// of iter kc orders all threads past iter kc-1's mma, so issuing into buffer
// (kc+1)&1 == (kc-1)&1 right after it is race-free).
// Static smem 46080B.  __launch_bounds__(256,2): 128-reg cap, 2 CTAs/SM.
// BN=160 divides 960/320/1280; A-tile L2 passes drop 2.5x vs BN=64.
// EPI: 0 bf16 (+bias) | 1 bf16 gelu | 2 fp32 += win-reversed | 3 fp32 += plain
// ---------------------------------------------------------------------------
#define LDA 40
#define G2_ASZ (128 * LDA)
#define G2_BSZ (160 * LDA)

template<int EPI, bool SHIFT>
__global__ __launch_bounds__(256, 2)
void k_gemm_mma(const bf16* __restrict__ A, const bf16* __restrict__ Wt,
                const float* __restrict__ bias, void* __restrict__ OutP,
                int K, int Nn) {
    __shared__ __align__(16) bf16 Asm[2][G2_ASZ];
    __shared__ __align__(16) bf16 Bsm[2][G2_BSZ];

    const int tid = threadIdx.x, lane = tid & 31, wid = tid >> 5;
    const int wm = wid & 3, wn = wid >> 2;           // 4m x 2n warps
    const int m0 = blockIdx.y * 128, n0 = blockIdx.x * 160;

    uint32_t sA[2] = { smem_to_u32(Asm[0]), smem_to_u32(Asm[1]) };
    uint32_t sB[2] = { smem_to_u32(Bsm[0]), smem_to_u32(Bsm[1]) };

    float acc[2][10][4];
    #pragma unroll
    for (int i = 0; i < 2; i++)
        #pragma unroll
        for (int j = 0; j < 10; j++)
            #pragma unroll
            for (int k = 0; k < 4; k++) acc[i][j][k] = 0.f;

    const int NC = K >> 5;

    auto issue = [&](int kc, int buf) {
        const bf16* Ag = A + (size_t)m0 * K + kc * 32;
        #pragma unroll
        for (int i = 0; i < 2; i++) {            // 128 rows x 4 x 16B = 512 ops
            int v = tid + i * 256;
            int row = v >> 2, c8 = (v & 3) * 8;
            cp_async16(sA[buf] + (uint32_t)(row * LDA + c8) * 2,
                       Ag + (size_t)row * K + c8);
        }
        const bf16* Bg = Wt + (size_t)n0 * K + kc * 32;
        #pragma unroll
        for (int i = 0; i < 3; i++) {            // 160 rows x 4 x 16B = 640 ops
            int v = tid + i * 256;
            if (v < 640) {
                int row = v >> 2, c8 = (v & 3) * 8;
                cp_async16(sB[buf] + (uint32_t)(row * LDA + c8) * 2,
                           Bg + (size_t)row * K + c8);
            }
        }
    };

    issue(0, 0); CP_COMMIT();

    for (int kc = 0; kc < NC; kc++) {
        int buf = kc & 1;
        CP_WAIT0();              // this thread's copies for chunk kc done
        __syncthreads();         // everyone's copies visible; iter kc-1 fully retired
        if (kc + 1 < NC) { issue(kc + 1, buf ^ 1); CP_COMMIT(); }

        #pragma unroll
        for (int ks = 0; ks < 2; ks++) {
            int k0 = ks * 16;
            uint32_t afr[2][4];
            #pragma unroll
            for (int mt = 0; mt < 2; mt++) {
                uint32_t addr = sA[buf] +
                    (uint32_t)(((wm * 32 + mt * 16 + (lane & 15)) * LDA)
                               + k0 + ((lane >> 4) * 8)) * 2;
                LDSM_X4(afr[mt][0], afr[mt][1], afr[mt][2], afr[mt][3], addr);
            }
            uint32_t bfr[10][2];
            #pragma unroll
            for (int p = 0; p < 5; p++) {
                uint32_t addr = sB[buf] +
                    (uint32_t)(((wn * 80 + p * 16 + ((lane >> 4) & 1) * 8 + (lane & 7)) * LDA)
                               + k0 + ((lane >> 3) & 1) * 8) * 2;
                uint32_t r0, r1, r2, r3;
                LDSM_X4(r0, r1, r2, r3, addr);
                bfr[2 * p][0] = r0;     bfr[2 * p][1] = r1;
                bfr[2 * p + 1][0] = r2; bfr[2 * p + 1][1] = r3;
            }
            #pragma unroll
            for (int mt = 0; mt < 2; mt++)
                #pragma unroll
                for (int nt = 0; nt < 10; nt++)
                    mma_16816(acc[mt][nt], afr[mt], bfr[nt]);
        }
    }

    const int qr = lane >> 2, qc = (lane & 3) * 2;
    #pragma unroll
    for (int nt = 0; nt < 10; nt++) {
        int gn = n0 + wn * 80 + nt * 8 + qc;
        float b0 = bias[gn], b1 = bias[gn + 1];
        #pragma unroll
        for (int mt = 0; mt < 2; mt++) {
            int gmA = m0 + wm * 32 + mt * 16 + qr;
            float v0 = acc[mt][nt][0] + b0;
            float v1 = acc[mt][nt][1] + b1;
            float v2 = acc[mt][nt][2] + b0;
            float v3 = acc[mt][nt][3] + b1;
            if (EPI == 1) {
                v0 = 0.5f * v0 * (1.f + erff(v0 * 0.70710678118654752f));
                v1 = 0.5f * v1 * (1.f + erff(v1 * 0.70710678118654752f));
                v2 = 0.5f * v2 * (1.f + erff(v2 * 0.70710678118654752f));
                v3 = 0.5f * v3 * (1.f + erff(v3 * 0.70710678118654752f));
            }
            if (EPI == 0 || EPI == 1) {
                bf16* Ob = (bf16*)OutP;
                *(__nv_bfloat162*)(Ob + (size_t)gmA * Nn + gn) = __floats2bfloat162_rn(v0, v1);
                *(__nv_bfloat162*)(Ob + (size_t)(gmA + 8) * Nn + gn) = __floats2bfloat162_rn(v2, v3);
            } else {
                float* Of = (float*)OutP;
                int r0 = (EPI == 2) ? win_src_row(gmA, SHIFT) : gmA;
                int r1 = (EPI == 2) ? win_src_row(gmA + 8, SHIFT) : (gmA + 8);
                float* p0 = Of + (size_t)r0 * 320 + gn;
                float* p1 = Of + (size_t)r1 * 320 + gn;
                p0[0] += v0; p0[1] += v1;
                p1[0] += v2; p1[1] += v3;
            }
        }
    }
}

// ---------------------------------------------------------------------------
// Warp-mma windowed attention: one warp per (window, head); 4 warps/block.
// (unchanged from passing R12 build)
// ---------------------------------------------------------------------------
#define ATT_LD 40

template<bool SHIFT>
__global__ __launch_bounds__(128)
void k_attn(const bf16* __restrict__ qkv,
            const float* __restrict__ biasTab,
            bf16* __restrict__ out) {
    __shared__ float bias_sh[1470];
    __shared__ __align__(16) bf16 kbuf[4][32 * ATT_LD];
    __shared__ __align__(16) bf16 qvbuf[4][32 * ATT_LD];   // q, then v

    int tid = threadIdx.x, lane = tid & 31, wrp = tid >> 5;
    for (int i = tid; i < 1470; i += 128) bias_sh[i] = biasTab[i];
    __syncthreads();

    int gwh = blockIdx.x * 4 + wrp;
    int win = gwh / 10;
    int head = gwh - win * 10;
    const bf16* base = qkv + (size_t)win * 32 * 960;
    bf16* ks = kbuf[wrp];
    bf16* qs = qvbuf[wrp];
    uint32_t ksu = smem_to_u32(ks), qsu = smem_to_u32(qs);

    #pragma unroll 4
    for (int m = 0; m < 32; m++) ks[m * ATT_LD + lane] = base[m * 960 + 320 + head * 32 + lane];
    #pragma unroll 4
    for (int m = 0; m < 32; m++)
        qs[m * ATT_LD + lane] =
            __float2bfloat16(__bfloat162float(base[m * 960 + head * 32 + lane]) * QK_SCALE);
    __syncwarp();

    uint32_t qa[2][2][4];
    #pragma unroll
    for (int mt = 0; mt < 2; mt++)
        #pragma unroll
        for (int kt = 0; kt < 2; kt++) {
            uint32_t addr = qsu +
                (uint32_t)(((mt * 16 + (lane & 15)) * ATT_LD) + kt * 16 + (lane >> 4) * 8) * 2;
            LDSM_X4(qa[mt][kt][0], qa[mt][kt][1], qa[mt][kt][2], qa[mt][kt][3], addr);
        }
    uint32_t kb[4][2][2];
    #pragma unroll
    for (int p = 0; p < 2; p++)
        #pragma unroll
        for (int kt = 0; kt < 2; kt++) {
            uint32_t addr = ksu +
                (uint32_t)(((p * 16 + ((lane >> 4) & 1) * 8 + (lane & 7)) * ATT_LD)
                           + kt * 16 + ((lane >> 3) & 1) * 8) * 2;
            uint32_t r0, r1, r2, r3;
            LDSM_X4(r0, r1, r2, r3, addr);
            kb[2 * p][kt][0] = r0;     kb[2 * p][kt][1] = r1;
            kb[2 * p + 1][kt][0] = r2; kb[2 * p + 1][kt][1] = r3;
        }

    float S[2][4][4];
    #pragma unroll
    for (int mt = 0; mt < 2; mt++)
        #pragma unroll
        for (int nt = 0; nt < 4; nt++) {
            #pragma unroll
            for (int e = 0; e < 4; e++) S[mt][nt][e] = 0.f;
            mma_16816(S[mt][nt], qa[mt][0], kb[nt][0]);
            mma_16816(S[mt][nt], qa[mt][1], kb[nt][1]);
        }

    __syncwarp();
    #pragma unroll 4
    for (int m = 0; m < 32; m++) qs[m * ATT_LD + lane] = base[m * 960 + 640 + head * 32 + lane];
    __syncwarp();

    const int g4 = lane >> 2, t2 = (lane & 3) * 2;
    int rtok[4], ctok[8];
    #pragma unroll
    for (int mt = 0; mt < 2; mt++)
        #pragma unroll
        for (int h = 0; h < 2; h++) rtok[mt * 2 + h] = mt * 16 + h * 8 + g4;
    #pragma unroll
    for (int nt = 0; nt < 4; nt++)
        #pragma unroll
        for (int e = 0; e < 2; e++) ctok[nt * 2 + e] = nt * 8 + t2 + e;

    int rreg[4], creg[8];
    if (SHIFT) {
        int wi = win & 511;
        int bd = (wi >> 6) << 2, bh = ((wi >> 3) & 7) << 2, bw = (wi & 7) << 1;
        #pragma unroll
        for (int i = 0; i < 4; i++) {
            int n = rtok[i];
            int d = bd + (n >> 3), h = bh + ((n >> 1) & 3), w = bw + (n & 1);
            rreg[i] = (d < 28 ? 0 : (d < 30 ? 1 : 2)) * 9
                    + (h < 28 ? 0 : (h < 30 ? 1 : 2)) * 3
                    + (w < 14 ? 0 : (w < 15 ? 1 : 2));
        }
        #pragma unroll
        for (int i = 0; i < 8; i++) {
            int n = ctok[i];
            int d = bd + (n >> 3), h = bh + ((n >> 1) & 3), w = bw + (n & 1);
            creg[i] = (d < 28 ? 0 : (d < 30 ? 1 : 2)) * 9
                    + (h < 28 ? 0 : (h < 30 ? 1 : 2)) * 3
                    + (w < 14 ? 0 : (w < 15 ? 1 : 2));
        }
    }

    #pragma unroll
    for (int mt = 0; mt < 2; mt++)
        #pragma unroll
        for (int nt = 0; nt < 4; nt++)
            #pragma unroll
            for (int h = 0; h < 2; h++)
                #pragma unroll
                for (int e = 0; e < 2; e++) {
                    int ri = mt * 2 + h, ci = nt * 2 + e;
                    int r = rtok[ri], c = ctok[ci];
                    int idx = ((r >> 3) - (c >> 3) + 3) * 21
                            + (((r >> 1) & 3) - ((c >> 1) & 3) + 3) * 3
                            + ((r & 1) - (c & 1) + 1);
                    float s = S[mt][nt][h * 2 + e] + bias_sh[idx * 10 + head];
                    if (SHIFT && rreg[ri] != creg[ci]) s -= 100.f;
                    S[mt][nt][h * 2 + e] = s;
                }

    float mx[4] = {-1e30f, -1e30f, -1e30f, -1e30f};
    #pragma unroll
    for (int mt = 0; mt < 2; mt++)
        #pragma unroll
        for (int nt = 0; nt < 4; nt++)
            #pragma unroll
            for (int h = 0; h < 2; h++) {
                mx[mt*2+h] = fmaxf(mx[mt*2+h], fmaxf(S[mt][nt][h*2], S[mt][nt][h*2+1]));
            }
    #pragma unroll
    for (int i = 0; i < 4; i++) {
        mx[i] = fmaxf(mx[i], __shfl_xor_sync(0xffffffffu, mx[i], 1));
        mx[i] = fmaxf(mx[i], __shfl_xor_sync(0xffffffffu, mx[i], 2));
    }
    float sm[4] = {0.f, 0.f, 0.f, 0.f};
    #pragma unroll
    for (int mt = 0; mt < 2; mt++)
        #pragma unroll
        for (int nt = 0; nt < 4; nt++)
            #pragma unroll
            for (int h = 0; h < 2; h++)
                #pragma unroll
                for (int e = 0; e < 2; e++) {
                    float ev = __expf(S[mt][nt][h*2+e] - mx[mt*2+h]);
                    S[mt][nt][h*2+e] = ev;
                    sm[mt*2+h] += ev;
                }
    #pragma unroll
    for (int i = 0; i < 4; i++) {
        sm[i] += __shfl_xor_sync(0xffffffffu, sm[i], 1);
        sm[i] += __shfl_xor_sync(0xffffffffu, sm[i], 2);
    }
    float inv[4];
    #pragma unroll
    for (int i = 0; i < 4; i++) inv[i] = 1.f / sm[i];

    uint32_t pa[2][2][4];
    #pragma unroll
    for (int mt = 0; mt < 2; mt++)
        #pragma unroll
        for (int kt = 0; kt < 2; kt++) {
            pa[mt][kt][0] = packbf2(S[mt][2*kt][0],   S[mt][2*kt][1]);
            pa[mt][kt][1] = packbf2(S[mt][2*kt][2],   S[mt][2*kt][3]);
            pa[mt][kt][2] = packbf2(S[mt][2*kt+1][0], S[mt][2*kt+1][1]);
            pa[mt][kt][3] = packbf2(S[mt][2*kt+1][2], S[mt][2*kt+1][3]);
        }

    uint32_t vb[4][2][2];
    #pragma unroll
    for (int p = 0; p < 2; p++)
        #pragma unroll
        for (int kt = 0; kt < 2; kt++) {
            uint32_t addr = qsu +
                (uint32_t)(((kt * 16 + ((lane >> 3) & 1) * 8 + (lane & 7)) * ATT_LD)
                           + (2 * p + ((lane >> 4) & 1)) * 8) * 2;
            uint32_t r0, r1, r2, r3;
            LDSM_X4_TRANS(r0, r1, r2, r3, addr);
            vb[2 * p][kt][0] = r0;     vb[2 * p][kt][1] = r1;
            vb[2 * p + 1][kt][0] = r2; vb[2 * p + 1][kt][1] = r3;
        }

    float O[2][4][4];
    #pragma unroll
    for (int mt = 0; mt < 2; mt++)
        #pragma unroll
        for (int nt = 0; nt < 4; nt++) {
            #pragma unroll
            for (int e = 0; e < 4; e++) O[mt][nt][e] = 0.f;
            mma_16816(O[mt][nt], pa[mt][0], vb[nt][0]);
            mma_16816(O[mt][nt], pa[mt][1], vb[nt][1]);
        }

    bf16* obase = out + (size_t)win * 32 * 320 + head * 32;
    #pragma unroll
    for (int mt = 0; mt < 2; mt++)
        #pragma unroll
        for (int nt = 0; nt < 4; nt++)
            #pragma unroll
            for (int h = 0; h < 2; h++) {
                int r = mt * 16 + h * 8 + g4;
                float iv = inv[mt * 2 + h];
                *(__nv_bfloat162*)(obase + (size_t)r * 320 + nt * 8 + t2) =
                    __floats2bfloat162_rn(O[mt][nt][h*2] * iv, O[mt][nt][h*2+1] * iv);
            }
}

// ---------------------------------------------------------------------------
// Host orchestration
// ---------------------------------------------------------------------------
static void run_block(bool shift, const float* const* p, bf16* wb,
                      float* t, bf16* xw, bf16* qkv, bf16* attn, bf16* mlp) {
    const float* ln1g = p[0];  const float* ln1b = p[1];
    const float* qkvb = p[3];  const float* bias = p[4];
    const float* projb = p[6];
    const float* ln2g = p[7];  const float* ln2b = p[8];
    const float* f1b = p[10];  const float* f2b = p[12];

    if (shift) k_ln<true, true ><<<16384, 256>>>(t, ln1g, ln1b, xw);
    else       k_ln<true, false><<<16384, 256>>>(t, ln1g, ln1b, xw);

    k_gemm_mma<0, false><<<dim3(6, 1024), 256>>>(xw, wb + WOFF_QKV, qkvb, qkv, 320, 960);

    if (shift) k_attn<true ><<<10240, 128>>>(qkv, bias, attn);
    else       k_attn<false><<<10240, 128>>>(qkv, bias, attn);

    if (shift) k_gemm_mma<2, true ><<<dim3(2, 1024), 256>>>(attn, wb + WOFF_PROJ, projb, t, 320, 320);
    else       k_gemm_mma<2, false><<<dim3(2, 1024), 256>>>(attn, wb + WOFF_PROJ, projb, t, 320, 320);

    k_ln<false, false><<<16384, 256>>>(t, ln2g, ln2b, xw);

    k_gemm_mma<1, false><<<dim3(8, 1024), 256>>>(xw, wb + WOFF_F1, f1b, mlp, 320, 1280);

    k_gemm_mma<3, false><<<dim3(2, 1024), 256>>>(mlp, wb + WOFF_F2, f2b, t, 1280, 320);
}

extern "C" void kernel_launch(void* const* d_in, const int* in_sizes, int n_in,
                              void* d_out, int out_size) {
    (void)in_sizes; (void)n_in; (void)out_size;
    const float* x = (const float*)d_in[0];

    void *pt, *pxw, *pqkv, *pattn, *pmlp, *pwb;
    cudaGetSymbolAddress(&pt,    g_t);
    cudaGetSymbolAddress(&pxw,   g_xw);
    cudaGetSymbolAddress(&pqkv,  g_qkv);
    cudaGetSymbolAddress(&pattn, g_attn);
    cudaGetSymbolAddress(&pmlp,  g_mlp);
    cudaGetSymbolAddress(&pwb,   g_wb);
    float* t   = (float*)pt;
    bf16* xw   = (bf16*)pxw;
    bf16* qkv  = (bf16*)pqkv;
    bf16* attn = (bf16*)pattn;
    bf16* mlp  = (bf16*)pmlp;
    bf16* wb0  = (bf16*)pwb;
    bf16* wb1  = wb0 + 1228800;

    const float* b1[13], * b2[13];
    for (int i = 0; i < 13; i++) b1[i] = (const float*)d_in[1 + i];
    for (int i = 0; i < 13; i++) b2[i] = (const float*)d_in[14 + i];

    k_wconv<<<dim3(10, 30), dim3(32, 8)>>>(b1[2],  wb0 + WOFF_QKV, 320, 960);
    k_wconv<<<dim3(10, 10), dim3(32, 8)>>>(b1[5],  wb0 + WOFF_PROJ, 320, 320);
    k_wconv<<<dim3(10, 40), dim3(32, 8)>>>(b1[9],  wb0 + WOFF_F1,  320, 1280);
    k_wconv<<<dim3(40, 10), dim3(32, 8)>>>(b1[11], wb0 + WOFF_F2, 1280, 320);
    k_wconv<<<dim3(10, 30), dim3(32, 8)>>>(b2[2],  wb1 + WOFF_QKV, 320, 960);
    k_wconv<<<dim3(10, 10), dim3(32, 8)>>>(b2[5],  wb1 + WOFF_PROJ, 320, 320);
    k_wconv<<<dim3(10, 40), dim3(32, 8)>>>(b2[9],  wb1 + WOFF_F1,  320, 1280);
    k_wconv<<<dim3(40, 10), dim3(32, 8)>>>(b2[11], wb1 + WOFF_F2, 1280, 320);

    // (B,C,L) -> (B,L,C)
    k_tin<<<dim3(L_ / 32, C_ / 32, B_), dim3(32, 8)>>>(x, t);

    run_block(false, b1, wb0, t, xw, qkv, attn, mlp);
    run_block(true,  b2, wb1, t, xw, qkv, attn, mlp);

    // (B,L,C) -> (B,C,L)
    k_tout<<<dim3(L_ / 32, C_ / 32, B_), dim3(32, 8)>>>(t, (float*)d_out);
}

// round 15
// speedup vs baseline: 4.5791x; 1.0001x over previous
#include <cuda_runtime.h>
#include <cuda_bf16.h>
#include <math.h>
#include <stdint.h>

// ---------------------------------------------------------------------------
// Problem constants
// ---------------------------------------------------------------------------
#define B_      8
#define C_      320
#define D_      32
#define H_      32
#define W_      16
#define L_      16384          // D*H*W
#define M_      131072         // B*L   (tokens)
#define QK_SCALE 0.17677669529663687f  // 1/sqrt(32)

typedef __nv_bfloat16 bf16;

// ---------------------------------------------------------------------------
// Portable tensor-core PTX helpers (sm_80+ ISA)
// ---------------------------------------------------------------------------
__device__ __forceinline__ uint32_t smem_to_u32(const void* p) {
    uint32_t a;
    asm("{ .reg .u64 t; cvta.to.shared.u64 t, %1; cvt.u32.u64 %0, t; }" : "=r"(a) : "l"(p));
    return a;
}
__device__ __forceinline__ void cp_async16(uint32_t dst, const void* src) {
    asm volatile("cp.async.cg.shared.global [%0], [%1], 16;" :: "r"(dst), "l"(src));
}
#define CP_COMMIT() asm volatile("cp.async.commit_group;" ::: "memory")
#define CP_WAIT0()  asm volatile("cp.async.wait_group 0;" ::: "memory")

#define LDSM_X4(r0, r1, r2, r3, a) \
    asm volatile("ldmatrix.sync.aligned.m8n8.x4.shared.b16 {%0,%1,%2,%3}, [%4];" \
                 : "=r"(r0), "=r"(r1), "=r"(r2), "=r"(r3) : "r"(a))
#define LDSM_X4_TRANS(r0, r1, r2, r3, a) \
    asm volatile("ldmatrix.sync.aligned.m8n8.x4.trans.shared.b16 {%0,%1,%2,%3}, [%4];" \
                 : "=r"(r0), "=r"(r1), "=r"(r2), "=r"(r3) : "r"(a))

__device__ __forceinline__ void mma_16816(float* c, const uint32_t* a, const uint32_t* b) {
    asm volatile(
        "mma.sync.aligned.m16n8k16.row.col.f32.bf16.bf16.f32 "
        "{%0,%1,%2,%3}, {%4,%5,%6,%7}, {%8,%9}, {%0,%1,%2,%3};"
        : "+f"(c[0]), "+f"(c[1]), "+f"(c[2]), "+f"(c[3])
        : "r"(a[0]), "r"(a[1]), "r"(a[2]), "r"(a[3]), "r"(b[0]), "r"(b[1]));
}
__device__ __forceinline__ uint32_t packbf2(float lo, float hi) {
    __nv_bfloat162 v = __floats2bfloat162_rn(lo, hi);
    return *(uint32_t*)&v;
}

// ---------------------------------------------------------------------------
// Scratch (static device globals)
// ---------------------------------------------------------------------------
__device__ float g_t   [(size_t)M_ * C_];      // residual stream fp32 (B,L,C)
__device__ bf16  g_xw  [(size_t)M_ * C_];      // LN output bf16
__device__ bf16  g_qkv [(size_t)M_ * 960];     // qkv bf16, windowed rows
__device__ bf16  g_attn[(size_t)M_ * C_];      // attention out bf16, windowed rows
__device__ bf16  g_mlp [(size_t)M_ * 1280];    // gelu(f1) out bf16
__device__ bf16  g_wb[2][1228800];             // [N,K] bf16 weights per block
#define WOFF_QKV 0
#define WOFF_PROJ 307200
#define WOFF_F1 409600
#define WOFF_F2 819200

// ---------------------------------------------------------------------------
// Window geometry
// ---------------------------------------------------------------------------
__device__ __forceinline__ int win_src_row(int r, bool shift) {
    int b   = r >> 14;
    int rem = r & 16383;
    int wi  = rem >> 5;
    int n   = rem & 31;
    int d = ((wi >> 6) << 2)        + (n >> 3);
    int h = (((wi >> 3) & 7) << 2)  + ((n >> 1) & 3);
    int w = ((wi & 7) << 1)         + (n & 1);
    if (shift) { d = (d + 2) & 31; h = (h + 2) & 31; w = (w + 1) & 15; }
    return (b << 14) + (d << 9) + (h << 4) + w;
}

// ---------------------------------------------------------------------------
// Transposes (fp32)
// ---------------------------------------------------------------------------
__global__ void k_tin(const float* __restrict__ x, float* __restrict__ t) {
    __shared__ float tile[32][33];
    int b = blockIdx.z, l0 = blockIdx.x * 32, c0 = blockIdx.y * 32;
    int tx = threadIdx.x, ty = threadIdx.y;
    #pragma unroll
    for (int i = ty; i < 32; i += 8)
        tile[i][tx] = x[((size_t)(b * C_ + c0 + i)) * L_ + l0 + tx];
    __syncthreads();
    #pragma unroll
    for (int i = ty; i < 32; i += 8)
        t[((size_t)(b * L_ + l0 + i)) * C_ + c0 + tx] = tile[tx][i];
}
__global__ void k_tout(const float* __restrict__ t, float* __restrict__ o) {
    __shared__ float tile[32][33];
    int b = blockIdx.z, l0 = blockIdx.x * 32, c0 = blockIdx.y * 32;
    int tx = threadIdx.x, ty = threadIdx.y;
    #pragma unroll
    for (int i = ty; i < 32; i += 8)
        tile[i][tx] = t[((size_t)(b * L_ + l0 + i)) * C_ + c0 + tx];
    __syncthreads();
    #pragma unroll
    for (int i = ty; i < 32; i += 8)
        o[((size_t)(b * C_ + c0 + i)) * L_ + l0 + tx] = tile[tx][i];
}

// ---------------------------------------------------------------------------
// Weight convert + transpose: W[K,N] fp32 -> out[N,K] bf16
// ---------------------------------------------------------------------------
__global__ void k_wconv(const float* __restrict__ Wm, bf16* __restrict__ out, int K, int N) {
    __shared__ float tile[32][33];
    int k0 = blockIdx.x * 32, n0 = blockIdx.y * 32;
    int tx = threadIdx.x, ty = threadIdx.y;
    #pragma unroll
    for (int i = ty; i < 32; i += 8)
        tile[i][tx] = Wm[(size_t)(k0 + i) * N + n0 + tx];
    __syncthreads();
    #pragma unroll
    for (int i = ty; i < 32; i += 8)
        out[(size_t)(n0 + i) * K + k0 + tx] = __float2bfloat16(tile[tx][i]);
}

// ---------------------------------------------------------------------------
// LayerNorm (one warp per token) -> bf16, optional windowed gather
// ---------------------------------------------------------------------------
template<bool WIN, bool SHIFT>
__global__ void k_ln(const float* __restrict__ t, const float* __restrict__ gam,
                     const float* __restrict__ bet, bf16* __restrict__ out) {
    int warp = (blockIdx.x * blockDim.x + threadIdx.x) >> 5;
    int lane = threadIdx.x & 31;
    if (warp >= M_) return;
    int src = WIN ? win_src_row(warp, SHIFT) : warp;
    const float* row = t + (size_t)src * C_;
    float v[10]; float s = 0.f;
    #pragma unroll
    for (int i = 0; i < 10; i++) { v[i] = row[lane + 32 * i]; s += v[i]; }
    #pragma unroll
    for (int o = 16; o; o >>= 1) s += __shfl_xor_sync(0xffffffffu, s, o);
    float mu = s * (1.f / C_); float var = 0.f;
    #pragma unroll
    for (int i = 0; i < 10; i++) { float d = v[i] - mu; var += d * d; }
    #pragma unroll
    for (int o = 16; o; o >>= 1) var += __shfl_xor_sync(0xffffffffu, var, o);
    float inv = rsqrtf(var * (1.f / C_) + 1e-5f);
    bf16* orow = out + (size_t)warp * C_;
    #pragma unroll
    for (int i = 0; i < 10; i++) {
        int c = lane + 32 * i;
        orow[c] = __float2bfloat16((v[i] - mu) * inv * gam[c] + bet[c]);
    }
}

// ---------------------------------------------------------------------------
// HMMA GEMM: BM=128, BN=160, BK=32.  256 threads (8 warps, 4m x 2n),
// warp tile 32x80.  2-stage cp.async, ONE barrier per chunk (the top barrier
// of iter kc orders all threads past iter kc-1's mma, so issuing into buffer
// (kc+1)&1 == (kc-1)&1 right after it is race-free).
// Static smem 46080B.  __launch_bounds__(256,2): 128-reg cap, 2 CTAs/SM.
// BN=160 divides 960/320/1280; A-tile L2 passes drop 2.5x vs BN=64.
// EPI: 0 bf16 (+bias) | 1 bf16 gelu | 2 fp32 += win-reversed | 3 fp32 += plain
// ---------------------------------------------------------------------------
#define LDA 40
#define G2_ASZ (128 * LDA)
#define G2_BSZ (160 * LDA)

template<int EPI, bool SHIFT>
__global__ __launch_bounds__(256, 2)
void k_gemm_mma(const bf16* __restrict__ A, const bf16* __restrict__ Wt,
                const float* __restrict__ bias, void* __restrict__ OutP,
                int K, int Nn) {
    __shared__ __align__(16) bf16 Asm[2][G2_ASZ];
    __shared__ __align__(16) bf16 Bsm[2][G2_BSZ];

    const int tid = threadIdx.x, lane = tid & 31, wid = tid >> 5;
    const int wm = wid & 3, wn = wid >> 2;           // 4m x 2n warps
    const int m0 = blockIdx.y * 128, n0 = blockIdx.x * 160;

    uint32_t sA[2] = { smem_to_u32(Asm[0]), smem_to_u32(Asm[1]) };
    uint32_t sB[2] = { smem_to_u32(Bsm[0]), smem_to_u32(Bsm[1]) };

    float acc[2][10][4];
    #pragma unroll
    for (int i = 0; i < 2; i++)
        #pragma unroll
        for (int j = 0; j < 10; j++)
            #pragma unroll
            for (int k = 0; k < 4; k++) acc[i][j][k] = 0.f;

    const int NC = K >> 5;

    auto issue = [&](int kc, int buf) {
        const bf16* Ag = A + (size_t)m0 * K + kc * 32;
        #pragma unroll
        for (int i = 0; i < 2; i++) {            // 128 rows x 4 x 16B = 512 ops
            int v = tid + i * 256;
            int row = v >> 2, c8 = (v & 3) * 8;
            cp_async16(sA[buf] + (uint32_t)(row * LDA + c8) * 2,
                       Ag + (size_t)row * K + c8);
        }
        const bf16* Bg = Wt + (size_t)n0 * K + kc * 32;
        #pragma unroll
        for (int i = 0; i < 3; i++) {            // 160 rows x 4 x 16B = 640 ops
            int v = tid + i * 256;
            if (v < 640) {
                int row = v >> 2, c8 = (v & 3) * 8;
                cp_async16(sB[buf] + (uint32_t)(row * LDA + c8) * 2,
                           Bg + (size_t)row * K + c8);
            }
        }
    };

    issue(0, 0); CP_COMMIT();

    for (int kc = 0; kc < NC; kc++) {
        int buf = kc & 1;
        CP_WAIT0();              // this thread's copies for chunk kc done
        __syncthreads();         // everyone's copies visible; iter kc-1 fully retired
        if (kc + 1 < NC) { issue(kc + 1, buf ^ 1); CP_COMMIT(); }

        #pragma unroll
        for (int ks = 0; ks < 2; ks++) {
            int k0 = ks * 16;
            uint32_t afr[2][4];
            #pragma unroll
            for (int mt = 0; mt < 2; mt++) {
                uint32_t addr = sA[buf] +
                    (uint32_t)(((wm * 32 + mt * 16 + (lane & 15)) * LDA)
                               + k0 + ((lane >> 4) * 8)) * 2;
                LDSM_X4(afr[mt][0], afr[mt][1], afr[mt][2], afr[mt][3], addr);
            }
            uint32_t bfr[10][2];
            #pragma unroll
            for (int p = 0; p < 5; p++) {
                uint32_t addr = sB[buf] +
                    (uint32_t)(((wn * 80 + p * 16 + ((lane >> 4) & 1) * 8 + (lane & 7)) * LDA)
                               + k0 + ((lane >> 3) & 1) * 8) * 2;
                uint32_t r0, r1, r2, r3;
                LDSM_X4(r0, r1, r2, r3, addr);
                bfr[2 * p][0] = r0;     bfr[2 * p][1] = r1;
                bfr[2 * p + 1][0] = r2; bfr[2 * p + 1][1] = r3;
            }
            #pragma unroll
            for (int mt = 0; mt < 2; mt++)
                #pragma unroll
                for (int nt = 0; nt < 10; nt++)
                    mma_16816(acc[mt][nt], afr[mt], bfr[nt]);
        }
    }

    const int qr = lane >> 2, qc = (lane & 3) * 2;
    #pragma unroll
    for (int nt = 0; nt < 10; nt++) {
        int gn = n0 + wn * 80 + nt * 8 + qc;
        float b0 = bias[gn], b1 = bias[gn + 1];
        #pragma unroll
        for (int mt = 0; mt < 2; mt++) {
            int gmA = m0 + wm * 32 + mt * 16 + qr;
            float v0 = acc[mt][nt][0] + b0;
            float v1 = acc[mt][nt][1] + b1;
            float v2 = acc[mt][nt][2] + b0;
            float v3 = acc[mt][nt][3] + b1;
            if (EPI == 1) {
                v0 = 0.5f * v0 * (1.f + erff(v0 * 0.70710678118654752f));
                v1 = 0.5f * v1 * (1.f + erff(v1 * 0.70710678118654752f));
                v2 = 0.5f * v2 * (1.f + erff(v2 * 0.70710678118654752f));
                v3 = 0.5f * v3 * (1.f + erff(v3 * 0.70710678118654752f));
            }
            if (EPI == 0 || EPI == 1) {
                bf16* Ob = (bf16*)OutP;
                *(__nv_bfloat162*)(Ob + (size_t)gmA * Nn + gn) = __floats2bfloat162_rn(v0, v1);
                *(__nv_bfloat162*)(Ob + (size_t)(gmA + 8) * Nn + gn) = __floats2bfloat162_rn(v2, v3);
            } else {
                float* Of = (float*)OutP;
                int r0 = (EPI == 2) ? win_src_row(gmA, SHIFT) : gmA;
                int r1 = (EPI == 2) ? win_src_row(gmA + 8, SHIFT) : (gmA + 8);
                float* p0 = Of + (size_t)r0 * 320 + gn;
                float* p1 = Of + (size_t)r1 * 320 + gn;
                p0[0] += v0; p0[1] += v1;
                p1[0] += v2; p1[1] += v3;
            }
        }
    }
}

// ---------------------------------------------------------------------------
// Warp-mma windowed attention: one warp per (window, head); 4 warps/block.
// (unchanged from passing R12 build)
// ---------------------------------------------------------------------------
#define ATT_LD 40

template<bool SHIFT>
__global__ __launch_bounds__(128)
void k_attn(const bf16* __restrict__ qkv,
            const float* __restrict__ biasTab,
            bf16* __restrict__ out) {
    __shared__ float bias_sh[1470];
    __shared__ __align__(16) bf16 kbuf[4][32 * ATT_LD];
    __shared__ __align__(16) bf16 qvbuf[4][32 * ATT_LD];   // q, then v

    int tid = threadIdx.x, lane = tid & 31, wrp = tid >> 5;
    for (int i = tid; i < 1470; i += 128) bias_sh[i] = biasTab[i];
    __syncthreads();

    int gwh = blockIdx.x * 4 + wrp;
    int win = gwh / 10;
    int head = gwh - win * 10;
    const bf16* base = qkv + (size_t)win * 32 * 960;
    bf16* ks = kbuf[wrp];
    bf16* qs = qvbuf[wrp];
    uint32_t ksu = smem_to_u32(ks), qsu = smem_to_u32(qs);

    #pragma unroll 4
    for (int m = 0; m < 32; m++) ks[m * ATT_LD + lane] = base[m * 960 + 320 + head * 32 + lane];
    #pragma unroll 4
    for (int m = 0; m < 32; m++)
        qs[m * ATT_LD + lane] =
            __float2bfloat16(__bfloat162float(base[m * 960 + head * 32 + lane]) * QK_SCALE);
    __syncwarp();

    uint32_t qa[2][2][4];
    #pragma unroll
    for (int mt = 0; mt < 2; mt++)
        #pragma unroll
        for (int kt = 0; kt < 2; kt++) {
            uint32_t addr = qsu +
                (uint32_t)(((mt * 16 + (lane & 15)) * ATT_LD) + kt * 16 + (lane >> 4) * 8) * 2;
            LDSM_X4(qa[mt][kt][0], qa[mt][kt][1], qa[mt][kt][2], qa[mt][kt][3], addr);
        }
    uint32_t kb[4][2][2];
    #pragma unroll
    for (int p = 0; p < 2; p++)
        #pragma unroll
        for (int kt = 0; kt < 2; kt++) {
            uint32_t addr = ksu +
                (uint32_t)(((p * 16 + ((lane >> 4) & 1) * 8 + (lane & 7)) * ATT_LD)
                           + kt * 16 + ((lane >> 3) & 1) * 8) * 2;
            uint32_t r0, r1, r2, r3;
            LDSM_X4(r0, r1, r2, r3, addr);
            kb[2 * p][kt][0] = r0;     kb[2 * p][kt][1] = r1;
            kb[2 * p + 1][kt][0] = r2; kb[2 * p + 1][kt][1] = r3;
        }

    float S[2][4][4];
    #pragma unroll
    for (int mt = 0; mt < 2; mt++)
        #pragma unroll
        for (int nt = 0; nt < 4; nt++) {
            #pragma unroll
            for (int e = 0; e < 4; e++) S[mt][nt][e] = 0.f;
            mma_16816(S[mt][nt], qa[mt][0], kb[nt][0]);
            mma_16816(S[mt][nt], qa[mt][1], kb[nt][1]);
        }

    __syncwarp();
    #pragma unroll 4
    for (int m = 0; m < 32; m++) qs[m * ATT_LD + lane] = base[m * 960 + 640 + head * 32 + lane];
    __syncwarp();

    const int g4 = lane >> 2, t2 = (lane & 3) * 2;
    int rtok[4], ctok[8];
    #pragma unroll
    for (int mt = 0; mt < 2; mt++)
        #pragma unroll
        for (int h = 0; h < 2; h++) rtok[mt * 2 + h] = mt * 16 + h * 8 + g4;
    #pragma unroll
    for (int nt = 0; nt < 4; nt++)
        #pragma unroll
        for (int e = 0; e < 2; e++) ctok[nt * 2 + e] = nt * 8 + t2 + e;

    int rreg[4], creg[8];
    if (SHIFT) {
        int wi = win & 511;
        int bd = (wi >> 6) << 2, bh = ((wi >> 3) & 7) << 2, bw = (wi & 7) << 1;
        #pragma unroll
        for (int i = 0; i < 4; i++) {
            int n = rtok[i];
            int d = bd + (n >> 3), h = bh + ((n >> 1) & 3), w = bw + (n & 1);
            rreg[i] = (d < 28 ? 0 : (d < 30 ? 1 : 2)) * 9
                    + (h < 28 ? 0 : (h < 30 ? 1 : 2)) * 3
                    + (w < 14 ? 0 : (w < 15 ? 1 : 2));
        }
        #pragma unroll
        for (int i = 0; i < 8; i++) {
            int n = ctok[i];
            int d = bd + (n >> 3), h = bh + ((n >> 1) & 3), w = bw + (n & 1);
            creg[i] = (d < 28 ? 0 : (d < 30 ? 1 : 2)) * 9
                    + (h < 28 ? 0 : (h < 30 ? 1 : 2)) * 3
                    + (w < 14 ? 0 : (w < 15 ? 1 : 2));
        }
    }

    #pragma unroll
    for (int mt = 0; mt < 2; mt++)
        #pragma unroll
        for (int nt = 0; nt < 4; nt++)
            #pragma unroll
            for (int h = 0; h < 2; h++)
                #pragma unroll
                for (int e = 0; e < 2; e++) {
                    int ri = mt * 2 + h, ci = nt * 2 + e;
                    int r = rtok[ri], c = ctok[ci];
                    int idx = ((r >> 3) - (c >> 3) + 3) * 21
                            + (((r >> 1) & 3) - ((c >> 1) & 3) + 3) * 3
                            + ((r & 1) - (c & 1) + 1);
                    float s = S[mt][nt][h * 2 + e] + bias_sh[idx * 10 + head];
                    if (SHIFT && rreg[ri] != creg[ci]) s -= 100.f;
                    S[mt][nt][h * 2 + e] = s;
                }

    float mx[4] = {-1e30f, -1e30f, -1e30f, -1e30f};
    #pragma unroll
    for (int mt = 0; mt < 2; mt++)
        #pragma unroll
        for (int nt = 0; nt < 4; nt++)
            #pragma unroll
            for (int h = 0; h < 2; h++) {
                mx[mt*2+h] = fmaxf(mx[mt*2+h], fmaxf(S[mt][nt][h*2], S[mt][nt][h*2+1]));
            }
    #pragma unroll
    for (int i = 0; i < 4; i++) {
        mx[i] = fmaxf(mx[i], __shfl_xor_sync(0xffffffffu, mx[i], 1));
        mx[i] = fmaxf(mx[i], __shfl_xor_sync(0xffffffffu, mx[i], 2));
    }
    float sm[4] = {0.f, 0.f, 0.f, 0.f};
    #pragma unroll
    for (int mt = 0; mt < 2; mt++)
        #pragma unroll
        for (int nt = 0; nt < 4; nt++)
            #pragma unroll
            for (int h = 0; h < 2; h++)
                #pragma unroll
                for (int e = 0; e < 2; e++) {
                    float ev = __expf(S[mt][nt][h*2+e] - mx[mt*2+h]);
                    S[mt][nt][h*2+e] = ev;
                    sm[mt*2+h] += ev;
                }
    #pragma unroll
    for (int i = 0; i < 4; i++) {
        sm[i] += __shfl_xor_sync(0xffffffffu, sm[i], 1);
        sm[i] += __shfl_xor_sync(0xffffffffu, sm[i], 2);
    }
    float inv[4];
    #pragma unroll
    for (int i = 0; i < 4; i++) inv[i] = 1.f / sm[i];

    uint32_t pa[2][2][4];
    #pragma unroll
    for (int mt = 0; mt < 2; mt++)
        #pragma unroll
        for (int kt = 0; kt < 2; kt++) {
            pa[mt][kt][0] = packbf2(S[mt][2*kt][0],   S[mt][2*kt][1]);
            pa[mt][kt][1] = packbf2(S[mt][2*kt][2],   S[mt][2*kt][3]);
            pa[mt][kt][2] = packbf2(S[mt][2*kt+1][0], S[mt][2*kt+1][1]);
            pa[mt][kt][3] = packbf2(S[mt][2*kt+1][2], S[mt][2*kt+1][3]);
        }

    uint32_t vb[4][2][2];
    #pragma unroll
    for (int p = 0; p < 2; p++)
        #pragma unroll
        for (int kt = 0; kt < 2; kt++) {
            uint32_t addr = qsu +
                (uint32_t)(((kt * 16 + ((lane >> 3) & 1) * 8 + (lane & 7)) * ATT_LD)
                           + (2 * p + ((lane >> 4) & 1)) * 8) * 2;
            uint32_t r0, r1, r2, r3;
            LDSM_X4_TRANS(r0, r1, r2, r3, addr);
            vb[2 * p][kt][0] = r0;     vb[2 * p][kt][1] = r1;
            vb[2 * p + 1][kt][0] = r2; vb[2 * p + 1][kt][1] = r3;
        }

    float O[2][4][4];
    #pragma unroll
    for (int mt = 0; mt < 2; mt++)
        #pragma unroll
        for (int nt = 0; nt < 4; nt++) {
            #pragma unroll
            for (int e = 0; e < 4; e++) O[mt][nt][e] = 0.f;
            mma_16816(O[mt][nt], pa[mt][0], vb[nt][0]);
            mma_16816(O[mt][nt], pa[mt][1], vb[nt][1]);
        }

    bf16* obase = out + (size_t)win * 32 * 320 + head * 32;
    #pragma unroll
    for (int mt = 0; mt < 2; mt++)
        #pragma unroll
        for (int nt = 0; nt < 4; nt++)
            #pragma unroll
            for (int h = 0; h < 2; h++) {
                int r = mt * 16 + h * 8 + g4;
                float iv = inv[mt * 2 + h];
                *(__nv_bfloat162*)(obase + (size_t)r * 320 + nt * 8 + t2) =
                    __floats2bfloat162_rn(O[mt][nt][h*2] * iv, O[mt][nt][h*2+1] * iv);
            }
}

// ---------------------------------------------------------------------------
// Host orchestration
// ---------------------------------------------------------------------------
static void run_block(bool shift, const float* const* p, bf16* wb,
                      float* t, bf16* xw, bf16* qkv, bf16* attn, bf16* mlp) {
    const float* ln1g = p[0];  const float* ln1b = p[1];
    const float* qkvb = p[3];  const float* bias = p[4];
    const float* projb = p[6];
    const float* ln2g = p[7];  const float* ln2b = p[8];
    const float* f1b = p[10];  const float* f2b = p[12];

    if (shift) k_ln<true, true ><<<16384, 256>>>(t, ln1g, ln1b, xw);
    else       k_ln<true, false><<<16384, 256>>>(t, ln1g, ln1b, xw);

    k_gemm_mma<0, false><<<dim3(6, 1024), 256>>>(xw, wb + WOFF_QKV, qkvb, qkv, 320, 960);

    if (shift) k_attn<true ><<<10240, 128>>>(qkv, bias, attn);
    else       k_attn<false><<<10240, 128>>>(qkv, bias, attn);

    if (shift) k_gemm_mma<2, true ><<<dim3(2, 1024), 256>>>(attn, wb + WOFF_PROJ, projb, t, 320, 320);
    else       k_gemm_mma<2, false><<<dim3(2, 1024), 256>>>(attn, wb + WOFF_PROJ, projb, t, 320, 320);

    k_ln<false, false><<<16384, 256>>>(t, ln2g, ln2b, xw);

    k_gemm_mma<1, false><<<dim3(8, 1024), 256>>>(xw, wb + WOFF_F1, f1b, mlp, 320, 1280);

    k_gemm_mma<3, false><<<dim3(2, 1024), 256>>>(mlp, wb + WOFF_F2, f2b, t, 1280, 320);
}

extern "C" void kernel_launch(void* const* d_in, const int* in_sizes, int n_in,
                              void* d_out, int out_size) {
    (void)in_sizes; (void)n_in; (void)out_size;
    const float* x = (const float*)d_in[0];

    void *pt, *pxw, *pqkv, *pattn, *pmlp, *pwb;
    cudaGetSymbolAddress(&pt,    g_t);
    cudaGetSymbolAddress(&pxw,   g_xw);
    cudaGetSymbolAddress(&pqkv,  g_qkv);
    cudaGetSymbolAddress(&pattn, g_attn);
    cudaGetSymbolAddress(&pmlp,  g_mlp);
    cudaGetSymbolAddress(&pwb,   g_wb);
    float* t   = (float*)pt;
    bf16* xw   = (bf16*)pxw;
    bf16* qkv  = (bf16*)pqkv;
    bf16* attn = (bf16*)pattn;
    bf16* mlp  = (bf16*)pmlp;
    bf16* wb0  = (bf16*)pwb;
    bf16* wb1  = wb0 + 1228800;

    const float* b1[13], * b2[13];
    for (int i = 0; i < 13; i++) b1[i] = (const float*)d_in[1 + i];
    for (int i = 0; i < 13; i++) b2[i] = (const float*)d_in[14 + i];

    k_wconv<<<dim3(10, 30), dim3(32, 8)>>>(b1[2],  wb0 + WOFF_QKV, 320, 960);
    k_wconv<<<dim3(10, 10), dim3(32, 8)>>>(b1[5],  wb0 + WOFF_PROJ, 320, 320);
    k_wconv<<<dim3(10, 40), dim3(32, 8)>>>(b1[9],  wb0 + WOFF_F1,  320, 1280);
    k_wconv<<<dim3(40, 10), dim3(32, 8)>>>(b1[11], wb0 + WOFF_F2, 1280, 320);
    k_wconv<<<dim3(10, 30), dim3(32, 8)>>>(b2[2],  wb1 + WOFF_QKV, 320, 960);
    k_wconv<<<dim3(10, 10), dim3(32, 8)>>>(b2[5],  wb1 + WOFF_PROJ, 320, 320);
    k_wconv<<<dim3(10, 40), dim3(32, 8)>>>(b2[9],  wb1 + WOFF_F1,  320, 1280);
    k_wconv<<<dim3(40, 10), dim3(32, 8)>>>(b2[11], wb1 + WOFF_F2, 1280, 320);

    // (B,C,L) -> (B,L,C)
    k_tin<<<dim3(L_ / 32, C_ / 32, B_), dim3(32, 8)>>>(x, t);

    run_block(false, b1, wb0, t, xw, qkv, attn, mlp);
    run_block(true,  b2, wb1, t, xw, qkv, attn, mlp);

    // (B,L,C) -> (B,C,L)
    k_tout<<<dim3(L_ / 32, C_ / 32, B_), dim3(32, 8)>>>(t, (float*)d_out);
}